// round 14
// baseline (speedup 1.0000x reference)
#include <cuda_runtime.h>
#include <cuda_bf16.h>
#include <cuda_fp16.h>
#include <mma.h>
using namespace nvcuda;

#define N_NODES 50000
#define N_PAD   50048       // padded to multiple of 128 for the TC GEMM
#define N_EDGES 800000
#define NT      850000      // edges + self loops
#define N_GRAPHS 256
#define F_IN    41
#define C1      256
#define C2      256
#define NEG_SLOPE 0.2f

// ---------------- scratch (device globals) ----------------
__device__ __align__(16) __half g_h1h[N_NODES * C1];   // h1, fp16 (only gat1 reads)
__device__ float g_al_s1[N_NODES * 2];
__device__ float g_al_d1[N_NODES * 2];
__device__ __align__(16) float g_out1[N_PAD * C1];     // pad rows stay zero
__device__ __align__(16) __half g_h2h[N_PAD * C2];     // h2, fp16 (gemm2 writes, gat2 reads)
__device__ float g_al_s2[N_NODES];
__device__ float g_al_d2[N_NODES];
__device__ __align__(16) float g_wvs[C2];
__device__ __align__(16) float g_wvd[C2];
__device__ __align__(16) float g_pool[N_GRAPHS * 256];
__device__ float g_cnt[N_GRAPHS];
__device__ float g_fc1[N_GRAPHS * 1024];
// CSR
__device__ int g_deg[N_NODES];
__device__ int g_rowstart[N_NODES + 1];
__device__ int g_cursor[N_NODES];
__device__ int g_csrc[NT];

__device__ __forceinline__ void red_add_v4(float* addr, float4 v) {
    asm volatile("red.global.add.v4.f32 [%0], {%1, %2, %3, %4};"
                 :: "l"(addr), "f"(v.x), "f"(v.y), "f"(v.z), "f"(v.w)
                 : "memory");
}
__device__ __forceinline__ float lrelu(float e) { return e > 0.f ? e : NEG_SLOPE * e; }

// unpack 8 halves (uint4) and FMA into acc with weight w
__device__ __forceinline__ void fma8h(float* acc, uint4 raw, float w) {
    __half2 hh[4];
    *(uint4*)hh = raw;
    float2 p0 = __half22float2(hh[0]);
    float2 p1 = __half22float2(hh[1]);
    float2 p2 = __half22float2(hh[2]);
    float2 p3 = __half22float2(hh[3]);
    acc[0] += w * p0.x; acc[1] += w * p0.y;
    acc[2] += w * p1.x; acc[3] += w * p1.y;
    acc[4] += w * p2.x; acc[5] += w * p2.y;
    acc[6] += w * p3.x; acc[7] += w * p3.y;
}

// ---------------- CSR build ----------------
__global__ void k_deg(const int* __restrict__ dst) {
    int i = blockIdx.x * blockDim.x + threadIdx.x;
    if (i >= NT) return;
    int d = (i < N_EDGES) ? dst[i] : i - N_EDGES;
    atomicAdd(&g_deg[d], 1);
}

// single-block: exclusive scan over g_deg + fused wvec (W2 @ a vectors) + pool zeroing.
// The scan occupies one SM for ~25us; the fused work rides along for free.
__global__ void k_scan(const float* __restrict__ W2, const float* __restrict__ as2,
                       const float* __restrict__ ad2) {
    int tid = threadIdx.x, lane = tid & 31, w = tid >> 5;

    // fused: zero pool/cnt (consumed by gat2 much later in the stream)
    for (int i = tid; i < N_GRAPHS * 256; i += 1024) g_pool[i] = 0.f;
    if (tid < N_GRAPHS) g_cnt[tid] = 0.f;

    // fused: w_s = W2 @ as2, w_d = W2 @ ad2 (warp w handles rows w, w+32, ...)
    for (int k = w; k < C2; k += 32) {
        float s = 0.f, d = 0.f;
        for (int j = lane; j < 256; j += 32) {
            float wv = W2[k * 256 + j];
            s += wv * as2[j];
            d += wv * ad2[j];
        }
#pragma unroll
        for (int o = 16; o > 0; o >>= 1) {
            s += __shfl_xor_sync(0xFFFFFFFFu, s, o);
            d += __shfl_xor_sync(0xFFFFFFFFu, d, o);
        }
        if (lane == 0) { g_wvs[k] = s; g_wvd[k] = d; }
    }

    // exclusive scan over g_deg
    __shared__ int warp_sums[32];
    __shared__ int s_carry;
    if (tid == 0) s_carry = 0;
    __syncthreads();
    for (int base = 0; base < N_NODES; base += 1024) {
        int i = base + tid;
        int v = (i < N_NODES) ? g_deg[i] : 0;
        int incl = v;
#pragma unroll
        for (int o = 1; o < 32; o <<= 1) {
            int t = __shfl_up_sync(0xFFFFFFFFu, incl, o);
            if (lane >= o) incl += t;
        }
        if (lane == 31) warp_sums[w] = incl;
        __syncthreads();
        if (w == 0) {
            int s = warp_sums[lane];
#pragma unroll
            for (int o = 1; o < 32; o <<= 1) {
                int t = __shfl_up_sync(0xFFFFFFFFu, s, o);
                if (lane >= o) s += t;
            }
            warp_sums[lane] = s;    // inclusive over warps
        }
        __syncthreads();
        int warp_off = (w == 0) ? 0 : warp_sums[w - 1];
        int excl = s_carry + warp_off + incl - v;
        if (i < N_NODES) { g_rowstart[i] = excl; g_cursor[i] = excl; }
        __syncthreads();
        if (tid == 0) s_carry += warp_sums[31];
        __syncthreads();
    }
    if (tid == 0) g_rowstart[N_NODES] = NT;
}

__global__ void k_fill(const int* __restrict__ src, const int* __restrict__ dst) {
    int i = blockIdx.x * blockDim.x + threadIdx.x;
    if (i >= NT) return;
    int s, d;
    if (i < N_EDGES) { s = src[i]; d = dst[i]; } else { s = d = i - N_EDGES; }
    int p = atomicAdd(&g_cursor[d], 1);
    g_csrc[p] = s;
}

// ---------------- layer 1 tiled GEMM + attention logits (fused) ----------------
// 64 nodes per 256-thread block; thread (tr,tc): rows tr*4..+3 x cols {tc+16i}.
#define G1_M 64
#define G1_SMEM (F_IN * C1 * 4 + G1_M * 43 * 4)
__global__ void __launch_bounds__(256) k_gemm1(const float* __restrict__ x,
                                               const float* __restrict__ W1,
                                               const float* __restrict__ a_s,
                                               const float* __restrict__ a_d) {
    extern __shared__ float sm[];
    float* W1s = sm;                                  // F_IN*C1
    float (*xs)[43] = (float (*)[43])(sm + F_IN * C1);
    int tid = threadIdx.x;
    int n0 = blockIdx.x * G1_M;

    for (int idx = tid; idx < (F_IN * C1) / 4; idx += 256)
        ((float4*)W1s)[idx] = ((const float4*)W1)[idx];
    for (int idx = tid; idx < G1_M * F_IN; idx += 256) {
        int r = idx / F_IN, c = idx % F_IN;
        int node = n0 + r;
        xs[r][c] = (node < N_NODES) ? x[node * F_IN + c] : 0.f;
    }
    __syncthreads();

    int tr = tid >> 4, tc = tid & 15;
    float acc[4][16];
#pragma unroll
    for (int j = 0; j < 4; j++)
#pragma unroll
        for (int i = 0; i < 16; i++) acc[j][i] = 0.f;

#pragma unroll 1
    for (int k = 0; k < F_IN; k++) {
        float a0 = xs[tr * 4 + 0][k];
        float a1 = xs[tr * 4 + 1][k];
        float a2 = xs[tr * 4 + 2][k];
        float a3 = xs[tr * 4 + 3][k];
        const float* wrow = &W1s[k * C1];
#pragma unroll
        for (int i = 0; i < 16; i++) {
            float b = wrow[tc + 16 * i];
            acc[0][i] += a0 * b;
            acc[1][i] += a1 * b;
            acc[2][i] += a2 * b;
            acc[3][i] += a3 * b;
        }
    }

    // store h1 (fp16) + per-thread partial logits (logits from fp32 accumulators)
    float sh0[4], sh1[4], dh0[4], dh1[4];
#pragma unroll
    for (int j = 0; j < 4; j++) { sh0[j] = sh1[j] = dh0[j] = dh1[j] = 0.f; }
#pragma unroll
    for (int i = 0; i < 16; i++) {
        int c = tc + 16 * i;
        float as = a_s[c], ad = a_d[c];
#pragma unroll
        for (int j = 0; j < 4; j++) {
            if (i < 8) { sh0[j] += acc[j][i] * as; dh0[j] += acc[j][i] * ad; }
            else       { sh1[j] += acc[j][i] * as; dh1[j] += acc[j][i] * ad; }
        }
    }
#pragma unroll
    for (int j = 0; j < 4; j++) {
        int node = n0 + tr * 4 + j;
        if (node < N_NODES) {
#pragma unroll
            for (int i = 0; i < 16; i++)
                g_h1h[node * C1 + tc + 16 * i] = __float2half_rn(acc[j][i]);
        }
    }
#pragma unroll
    for (int o = 8; o > 0; o >>= 1) {
#pragma unroll
        for (int j = 0; j < 4; j++) {
            sh0[j] += __shfl_xor_sync(0xFFFFFFFFu, sh0[j], o);
            sh1[j] += __shfl_xor_sync(0xFFFFFFFFu, sh1[j], o);
            dh0[j] += __shfl_xor_sync(0xFFFFFFFFu, dh0[j], o);
            dh1[j] += __shfl_xor_sync(0xFFFFFFFFu, dh1[j], o);
        }
    }
    if (tc == 0) {
#pragma unroll
        for (int j = 0; j < 4; j++) {
            int node = n0 + tr * 4 + j;
            if (node < N_NODES) {
                g_al_s1[node * 2]     = sh0[j];  g_al_s1[node * 2 + 1] = sh1[j];
                g_al_d1[node * 2]     = dh0[j];  g_al_d1[node * 2 + 1] = dh1[j];
            }
        }
    }
}

// ---------------- layer 1 fused softmax+gather (weights hoisted) + al2 epilogue ----------------
__global__ void k_gat1(const float* __restrict__ b1) {
    int n = blockIdx.x * 8 + (threadIdx.x >> 5);
    int lane = threadIdx.x & 31;
    if (n >= N_NODES) return;
    int row = g_rowstart[n], end = g_rowstart[n + 1];
    int h = lane >> 4;
    float alD0 = g_al_d1[n * 2], alD1 = g_al_d1[n * 2 + 1];

    float den = 0.f;
    float acc[8] = {0.f, 0.f, 0.f, 0.f, 0.f, 0.f, 0.f, 0.f};
    for (int j0 = row; j0 < end; j0 += 32) {
        int idx = j0 + lane;
        bool valid = idx < end;
        int sj = valid ? __ldg(&g_csrc[idx]) : 0;
        // lane computes BOTH heads' weights for ITS edge (parallel across lanes)
        float w0l = 0.f, w1l = 0.f;
        if (valid) {
            float as0 = __ldg(&g_al_s1[sj * 2]);
            float as1 = __ldg(&g_al_s1[sj * 2 + 1]);
            w0l = __expf(lrelu(as0 + alD0));
            w1l = __expf(lrelu(as1 + alD1));
        }
        int cnt = min(32, end - j0);
        int k = 0;
        for (; k + 1 < cnt; k += 2) {
            int s0 = __shfl_sync(0xFFFFFFFFu, sj, k);
            int s1 = __shfl_sync(0xFFFFFFFFu, sj, k + 1);
            float w0a = __shfl_sync(0xFFFFFFFFu, w0l, k);
            float w1a = __shfl_sync(0xFFFFFFFFu, w1l, k);
            float w0b = __shfl_sync(0xFFFFFFFFu, w0l, k + 1);
            float w1b = __shfl_sync(0xFFFFFFFFu, w1l, k + 1);
            uint4 r0 = *(const uint4*)&g_h1h[s0 * C1 + lane * 8];
            uint4 r1 = *(const uint4*)&g_h1h[s1 * C1 + lane * 8];
            float wA = h ? w1a : w0a;
            float wB = h ? w1b : w0b;
            den += wA + wB;
            fma8h(acc, r0, wA);
            fma8h(acc, r1, wB);
        }
        if (k < cnt) {
            int s = __shfl_sync(0xFFFFFFFFu, sj, k);
            float w0a = __shfl_sync(0xFFFFFFFFu, w0l, k);
            float w1a = __shfl_sync(0xFFFFFFFFu, w1l, k);
            float wA = h ? w1a : w0a;
            den += wA;
            fma8h(acc, *(const uint4*)&g_h1h[s * C1 + lane * 8], wA);
        }
    }
    float inv = 1.f / (den + 1e-16f);
    int c0 = lane * 8;
    float4 o0, o1;
    o0.x = fmaxf(acc[0] * inv + b1[c0 + 0], 0.f);
    o0.y = fmaxf(acc[1] * inv + b1[c0 + 1], 0.f);
    o0.z = fmaxf(acc[2] * inv + b1[c0 + 2], 0.f);
    o0.w = fmaxf(acc[3] * inv + b1[c0 + 3], 0.f);
    o1.x = fmaxf(acc[4] * inv + b1[c0 + 4], 0.f);
    o1.y = fmaxf(acc[5] * inv + b1[c0 + 5], 0.f);
    o1.z = fmaxf(acc[6] * inv + b1[c0 + 6], 0.f);
    o1.w = fmaxf(acc[7] * inv + b1[c0 + 7], 0.f);
    *(float4*)&g_out1[n * C1 + c0] = o0;
    *(float4*)&g_out1[n * C1 + c0 + 4] = o1;

    // fused al2: al_s2[n] = relu(out1[n]) . (W2 @ as2)  (likewise d)
    float4 ws0 = *(const float4*)&g_wvs[c0], ws1 = *(const float4*)&g_wvs[c0 + 4];
    float4 wd0 = *(const float4*)&g_wvd[c0], wd1 = *(const float4*)&g_wvd[c0 + 4];
    float ps = o0.x * ws0.x + o0.y * ws0.y + o0.z * ws0.z + o0.w * ws0.w
             + o1.x * ws1.x + o1.y * ws1.y + o1.z * ws1.z + o1.w * ws1.w;
    float pd = o0.x * wd0.x + o0.y * wd0.y + o0.z * wd0.z + o0.w * wd0.w
             + o1.x * wd1.x + o1.y * wd1.y + o1.z * wd1.z + o1.w * wd1.w;
#pragma unroll
    for (int o = 16; o > 0; o >>= 1) {
        ps += __shfl_xor_sync(0xFFFFFFFFu, ps, o);
        pd += __shfl_xor_sync(0xFFFFFFFFu, pd, o);
    }
    if (lane == 0) { g_al_s2[n] = ps; g_al_d2[n] = pd; }
}

// ---------------- tf32 tensor-core GEMM, fp16 output: g_h2h = g_out1 @ W2 ----------------
#define TCM 128
#define TCN 128
#define TCK 32
__global__ void __launch_bounds__(256) k_gemm2(const float* __restrict__ A,
                                               const float* __restrict__ B,
                                               __half* __restrict__ C) {
    __shared__ __align__(16) float As[TCM][TCK + 4];   // 18.4 KB
    __shared__ __align__(16) float Bs[TCK][TCN + 4];   // 16.9 KB
    __shared__ __align__(16) float Epi[8][256];        // 8 KB: per-warp 16x16 patch
    int tid = threadIdx.x;
    int bm = blockIdx.x * TCM, bn = blockIdx.y * TCN;
    int wid = tid >> 5, lane = tid & 31;
    int warp_m = (wid >> 1) * 32, warp_n = (wid & 1) * 64;

    wmma::fragment<wmma::accumulator, 16, 16, 8, float> c_frag[2][4];
#pragma unroll
    for (int i = 0; i < 2; i++)
#pragma unroll
        for (int j = 0; j < 4; j++) wmma::fill_fragment(c_frag[i][j], 0.f);

    for (int k0 = 0; k0 < 256; k0 += TCK) {
#pragma unroll
        for (int p = 0; p < 4; p++) {
            int r = (tid >> 3) + p * 32;
            int c4 = tid & 7;
            float4 v = *(const float4*)&A[(size_t)(bm + r) * 256 + k0 + c4 * 4];
            *(float4*)&As[r][c4 * 4] = v;
        }
#pragma unroll
        for (int p = 0; p < 4; p++) {
            int r = (tid >> 5) + p * 8;
            int c4 = tid & 31;
            float4 v = *(const float4*)&B[(size_t)(k0 + r) * 256 + bn + c4 * 4];
            *(float4*)&Bs[r][c4 * 4] = v;
        }
        __syncthreads();

#pragma unroll
        for (int kk = 0; kk < TCK; kk += 8) {
            wmma::fragment<wmma::matrix_a, 16, 16, 8, wmma::precision::tf32, wmma::row_major> a_frag[2];
            wmma::fragment<wmma::matrix_b, 16, 16, 8, wmma::precision::tf32, wmma::row_major> b_frag[4];
#pragma unroll
            for (int i = 0; i < 2; i++) {
                wmma::load_matrix_sync(a_frag[i], &As[warp_m + i * 16][kk], TCK + 4);
#pragma unroll
                for (int t = 0; t < a_frag[i].num_elements; t++)
                    a_frag[i].x[t] = wmma::__float_to_tf32(a_frag[i].x[t]);
            }
#pragma unroll
            for (int j = 0; j < 4; j++) {
                wmma::load_matrix_sync(b_frag[j], &Bs[kk][warp_n + j * 16], TCN + 4);
#pragma unroll
                for (int t = 0; t < b_frag[j].num_elements; t++)
                    b_frag[j].x[t] = wmma::__float_to_tf32(b_frag[j].x[t]);
            }
#pragma unroll
            for (int i = 0; i < 2; i++)
#pragma unroll
                for (int j = 0; j < 4; j++)
                    wmma::mma_sync(c_frag[i][j], a_frag[i], b_frag[j], c_frag[i][j]);
        }
        __syncthreads();
    }

    // epilogue: stage each 16x16 fragment through smem, convert to fp16, store
    float* patch = &Epi[wid][0];
    int er = lane >> 1, ec = (lane & 1) * 8;   // each lane: 8 floats of one row
#pragma unroll
    for (int i = 0; i < 2; i++)
#pragma unroll
        for (int j = 0; j < 4; j++) {
            wmma::store_matrix_sync(patch, c_frag[i][j], 16, wmma::mem_row_major);
            __syncwarp();
            float4 a = *(float4*)&patch[er * 16 + ec];
            float4 b = *(float4*)&patch[er * 16 + ec + 4];
            __half2 hh[4];
            hh[0] = __floats2half2_rn(a.x, a.y);
            hh[1] = __floats2half2_rn(a.z, a.w);
            hh[2] = __floats2half2_rn(b.x, b.y);
            hh[3] = __floats2half2_rn(b.z, b.w);
            size_t off = (size_t)(bm + warp_m + i * 16 + er) * 256 + bn + warp_n + j * 16 + ec;
            *(uint4*)&C[off] = *(uint4*)hh;
            __syncwarp();
        }
}

// ---------------- layer 2 fused softmax+gather (weights hoisted) + bias/relu + pool ----------------
__global__ void k_gat2(const float* __restrict__ b2, const int* __restrict__ batch) {
    int n = blockIdx.x * 8 + (threadIdx.x >> 5);
    int lane = threadIdx.x & 31;
    if (n >= N_NODES) return;
    int row = g_rowstart[n], end = g_rowstart[n + 1];
    float alD = g_al_d2[n];

    float den = 0.f;
    float acc[8] = {0.f, 0.f, 0.f, 0.f, 0.f, 0.f, 0.f, 0.f};
    for (int j0 = row; j0 < end; j0 += 32) {
        int idx = j0 + lane;
        bool valid = idx < end;
        int sj = valid ? __ldg(&g_csrc[idx]) : 0;
        float wl = valid ? __expf(lrelu(__ldg(&g_al_s2[sj]) + alD)) : 0.f;
        int cnt = min(32, end - j0);
        int k = 0;
        for (; k + 1 < cnt; k += 2) {
            int s0 = __shfl_sync(0xFFFFFFFFu, sj, k);
            int s1 = __shfl_sync(0xFFFFFFFFu, sj, k + 1);
            float w0 = __shfl_sync(0xFFFFFFFFu, wl, k);
            float w1 = __shfl_sync(0xFFFFFFFFu, wl, k + 1);
            uint4 r0 = *(const uint4*)&g_h2h[s0 * C2 + lane * 8];
            uint4 r1 = *(const uint4*)&g_h2h[s1 * C2 + lane * 8];
            den += w0 + w1;
            fma8h(acc, r0, w0);
            fma8h(acc, r1, w1);
        }
        if (k < cnt) {
            int s = __shfl_sync(0xFFFFFFFFu, sj, k);
            float w = __shfl_sync(0xFFFFFFFFu, wl, k);
            den += w;
            fma8h(acc, *(const uint4*)&g_h2h[s * C2 + lane * 8], w);
        }
    }
    float inv = 1.f / (den + 1e-16f);
    int c0 = lane * 8;
    float4 o0, o1;
    o0.x = fmaxf(acc[0] * inv + b2[c0 + 0], 0.f);
    o0.y = fmaxf(acc[1] * inv + b2[c0 + 1], 0.f);
    o0.z = fmaxf(acc[2] * inv + b2[c0 + 2], 0.f);
    o0.w = fmaxf(acc[3] * inv + b2[c0 + 3], 0.f);
    o1.x = fmaxf(acc[4] * inv + b2[c0 + 4], 0.f);
    o1.y = fmaxf(acc[5] * inv + b2[c0 + 5], 0.f);
    o1.z = fmaxf(acc[6] * inv + b2[c0 + 6], 0.f);
    o1.w = fmaxf(acc[7] * inv + b2[c0 + 7], 0.f);
    int g = batch[n];
    red_add_v4(&g_pool[g * 256 + c0], o0);
    red_add_v4(&g_pool[g * 256 + c0 + 4], o1);
    if (lane == 0) atomicAdd(&g_cnt[g], 1.0f);
}

// ---------------- MLP head ----------------
__global__ void k_mlp1(const float* __restrict__ fw, const float* __restrict__ fb) {
    int g = blockIdx.x >> 2, q = blockIdx.x & 3;
    int t = threadIdx.x;
    __shared__ float grow[256];
    float inv = 1.0f / fmaxf(g_cnt[g], 1.0f);
    grow[t] = g_pool[g * 256 + t] * inv;
    __syncthreads();
    int col = q * 256 + t;
    float acc = fb[col];
#pragma unroll 8
    for (int k = 0; k < 256; k++) acc += grow[k] * fw[k * 1024 + col];
    g_fc1[g * 1024 + col] = fmaxf(acc, 0.f);
}

__global__ void k_mlp2(const float* __restrict__ fw, const float* __restrict__ fb,
                       float* __restrict__ out) {
    int g = blockIdx.x;
    int t = threadIdx.x; // 128
    __shared__ float row[1024];
    for (int k = t; k < 1024; k += 128) row[k] = g_fc1[g * 1024 + k];
    __syncthreads();
    float acc = fb[t];
#pragma unroll 8
    for (int k = 0; k < 1024; k++) acc += row[k] * fw[k * 128 + t];
    out[g * 128 + t] = acc;
}

// ---------------- host launcher ----------------
static void* sym(const void* s) {
    void* p = nullptr;
    cudaGetSymbolAddress(&p, s);
    return p;
}

extern "C" void kernel_launch(void* const* d_in, const int* in_sizes, int n_in,
                              void* d_out, int out_size) {
    const float* x      = (const float*)d_in[0];
    const int*   src    = (const int*)d_in[1];
    const int*   dst    = (const int*)d_in[2];
    const int*   batch  = (const int*)d_in[3];
    const float* W1     = (const float*)d_in[4];
    const float* a_src1 = (const float*)d_in[5];
    const float* a_dst1 = (const float*)d_in[6];
    const float* b1     = (const float*)d_in[7];
    const float* W2     = (const float*)d_in[8];
    const float* a_src2 = (const float*)d_in[9];
    const float* a_dst2 = (const float*)d_in[10];
    const float* b2     = (const float*)d_in[11];
    const float* fc1_w  = (const float*)d_in[12];
    const float* fc1_b  = (const float*)d_in[13];
    const float* fc2_w  = (const float*)d_in[14];
    const float* fc2_b  = (const float*)d_in[15];
    float* out = (float*)d_out;

    static bool attr_set = false;
    if (!attr_set) {
        cudaFuncSetAttribute(k_gemm1, cudaFuncAttributeMaxDynamicSharedMemorySize, G1_SMEM);
        attr_set = true;
    }

    // single memset (pool/cnt zeroing folded into k_scan)
    cudaMemsetAsync(sym(g_deg), 0, N_NODES * sizeof(int));

    // CSR build (+ fused wvec + pool zero inside k_scan)
    k_deg<<<(NT + 255) / 256, 256>>>(dst);
    k_scan<<<1, 1024>>>(W2, a_src2, a_dst2);
    k_fill<<<(NT + 255) / 256, 256>>>(src, dst);

    // layer 1
    k_gemm1<<<(N_NODES + G1_M - 1) / G1_M, 256, G1_SMEM>>>(x, W1, a_src1, a_dst1);
    k_gat1<<<(N_NODES + 7) / 8, 256>>>(b1);

    // layer 2 (tf32 tensor cores, fp16 output, padded rows)
    float* d_o1 = (float*)sym(g_out1);
    __half* d_h2h = (__half*)sym(g_h2h);
    dim3 g2(N_PAD / TCM, 256 / TCN);
    k_gemm2<<<g2, 256>>>(d_o1, W2, d_h2h);
    k_gat2<<<(N_NODES + 7) / 8, 256>>>(b2, batch);

    // MLP
    k_mlp1<<<N_GRAPHS * 4, 256>>>(fc1_w, fc1_b);
    k_mlp2<<<N_GRAPHS, 128>>>(fc2_w, fc2_b, out);
}

// round 15
// speedup vs baseline: 1.0437x; 1.0437x over previous
#include <cuda_runtime.h>
#include <cuda_bf16.h>
#include <cuda_fp16.h>
#include <mma.h>
using namespace nvcuda;

#define N_NODES 50000
#define N_PAD   50048       // padded to multiple of 128 for the TC GEMM
#define N_EDGES 800000
#define NT      850000      // edges + self loops
#define N_GRAPHS 256
#define F_IN    41
#define C1      256
#define C2      256
#define NEG_SLOPE 0.2f

// ---------------- scratch (device globals) ----------------
__device__ __align__(16) __half g_h1h[N_NODES * C1];   // h1, fp16 (only gat1 reads)
__device__ float g_al_s1[N_NODES * 2];
__device__ float g_al_d1[N_NODES * 2];
__device__ __align__(16) float g_out1[N_PAD * C1];     // pad rows stay zero
__device__ __align__(16) __half g_h2h[N_PAD * C2];     // h2, fp16 (gemm2 writes, gat2 reads)
__device__ float g_al_s2[N_NODES];
__device__ float g_al_d2[N_NODES];
__device__ __align__(16) float g_wvs[C2];
__device__ __align__(16) float g_wvd[C2];
__device__ __align__(16) float g_pool[N_GRAPHS * 256];
__device__ float g_cnt[N_GRAPHS];
__device__ float g_fc1[N_GRAPHS * 1024];
// CSR
__device__ int g_deg[N_NODES];
__device__ int g_rowstart[N_NODES + 1];
__device__ int g_cursor[N_NODES];
__device__ int g_csrc[NT];

__device__ __forceinline__ void red_add_v4(float* addr, float4 v) {
    asm volatile("red.global.add.v4.f32 [%0], {%1, %2, %3, %4};"
                 :: "l"(addr), "f"(v.x), "f"(v.y), "f"(v.z), "f"(v.w)
                 : "memory");
}
__device__ __forceinline__ float lrelu(float e) { return e > 0.f ? e : NEG_SLOPE * e; }

// unpack 8 halves (uint4) and FMA into acc with weight w
__device__ __forceinline__ void fma8h(float* acc, uint4 raw, float w) {
    __half2 hh[4];
    *(uint4*)hh = raw;
    float2 p0 = __half22float2(hh[0]);
    float2 p1 = __half22float2(hh[1]);
    float2 p2 = __half22float2(hh[2]);
    float2 p3 = __half22float2(hh[3]);
    acc[0] += w * p0.x; acc[1] += w * p0.y;
    acc[2] += w * p1.x; acc[3] += w * p1.y;
    acc[4] += w * p2.x; acc[5] += w * p2.y;
    acc[6] += w * p3.x; acc[7] += w * p3.y;
}

// ---------------- CSR degree histogram + fused wvec / pool zeroing ----------------
// 3321 blocks; blocks 0-31 additionally compute wvec rows (warp per row),
// blocks 32-95 zero g_pool, block 96 zeros g_cnt. All parallel.
__global__ void k_deg(const int* __restrict__ dst, const float* __restrict__ W2,
                      const float* __restrict__ as2, const float* __restrict__ ad2) {
    int tid = threadIdx.x;
    int i = blockIdx.x * blockDim.x + tid;
    if (i < NT) {
        int d = (i < N_EDGES) ? dst[i] : i - N_EDGES;
        atomicAdd(&g_deg[d], 1);
    }
    if (blockIdx.x < 32) {
        // wvec: w_s = W2 @ as2, w_d = W2 @ ad2 ; row k = blockIdx*8 + warp
        int k = blockIdx.x * 8 + (tid >> 5);
        int lane = tid & 31;
        float s = 0.f, d = 0.f;
#pragma unroll
        for (int j = lane; j < 256; j += 32) {
            float wv = W2[k * 256 + j];
            s += wv * as2[j];
            d += wv * ad2[j];
        }
#pragma unroll
        for (int o = 16; o > 0; o >>= 1) {
            s += __shfl_xor_sync(0xFFFFFFFFu, s, o);
            d += __shfl_xor_sync(0xFFFFFFFFu, d, o);
        }
        if (lane == 0) { g_wvs[k] = s; g_wvd[k] = d; }
    } else if (blockIdx.x < 96) {
        // zero pool: 64 blocks x 256 threads x 1 float4 = 65536 floats
        int idx = (blockIdx.x - 32) * 256 + tid;
        ((float4*)g_pool)[idx] = make_float4(0.f, 0.f, 0.f, 0.f);
    } else if (blockIdx.x == 96) {
        if (tid < N_GRAPHS) g_cnt[tid] = 0.f;
    }
}

// single-block exclusive scan over g_deg -> g_rowstart, g_cursor
__global__ void k_scan() {
    __shared__ int warp_sums[32];
    __shared__ int s_carry;
    int tid = threadIdx.x, lane = tid & 31, w = tid >> 5;
    if (tid == 0) s_carry = 0;
    __syncthreads();
    for (int base = 0; base < N_NODES; base += 1024) {
        int i = base + tid;
        int v = (i < N_NODES) ? g_deg[i] : 0;
        int incl = v;
#pragma unroll
        for (int o = 1; o < 32; o <<= 1) {
            int t = __shfl_up_sync(0xFFFFFFFFu, incl, o);
            if (lane >= o) incl += t;
        }
        if (lane == 31) warp_sums[w] = incl;
        __syncthreads();
        if (w == 0) {
            int s = warp_sums[lane];
#pragma unroll
            for (int o = 1; o < 32; o <<= 1) {
                int t = __shfl_up_sync(0xFFFFFFFFu, s, o);
                if (lane >= o) s += t;
            }
            warp_sums[lane] = s;    // inclusive over warps
        }
        __syncthreads();
        int warp_off = (w == 0) ? 0 : warp_sums[w - 1];
        int excl = s_carry + warp_off + incl - v;
        if (i < N_NODES) { g_rowstart[i] = excl; g_cursor[i] = excl; }
        __syncthreads();
        if (tid == 0) s_carry += warp_sums[31];
        __syncthreads();
    }
    if (tid == 0) g_rowstart[N_NODES] = NT;
}

__global__ void k_fill(const int* __restrict__ src, const int* __restrict__ dst) {
    int i = blockIdx.x * blockDim.x + threadIdx.x;
    if (i >= NT) return;
    int s, d;
    if (i < N_EDGES) { s = src[i]; d = dst[i]; } else { s = d = i - N_EDGES; }
    int p = atomicAdd(&g_cursor[d], 1);
    g_csrc[p] = s;
}

// ---------------- layer 1 tiled GEMM + attention logits (fused) ----------------
// 32 nodes per 256-thread block; thread (tr,tc): rows tr*2..+1, cols {tc*4+64i ..+3}.
// Vector LDS.128 on W1 rows (conflict-free), vector STG.64 on h1h.
#define G1_M 32
#define G1_SMEM (F_IN * C1 * 4 + G1_M * 43 * 4)
__global__ void __launch_bounds__(256) k_gemm1(const float* __restrict__ x,
                                               const float* __restrict__ W1,
                                               const float* __restrict__ a_s,
                                               const float* __restrict__ a_d) {
    extern __shared__ float sm[];
    float* W1s = sm;                                  // F_IN*C1
    float (*xs)[43] = (float (*)[43])(sm + F_IN * C1);
    int tid = threadIdx.x;
    int n0 = blockIdx.x * G1_M;

    for (int idx = tid; idx < (F_IN * C1) / 4; idx += 256)
        ((float4*)W1s)[idx] = ((const float4*)W1)[idx];
    for (int idx = tid; idx < G1_M * F_IN; idx += 256) {
        int r = idx / F_IN, c = idx % F_IN;
        int node = n0 + r;
        xs[r][c] = (node < N_NODES) ? x[node * F_IN + c] : 0.f;
    }
    __syncthreads();

    int tr = tid >> 4, tc = tid & 15;
    int r0 = tr * 2, r1 = r0 + 1;
    float4 acc0[4], acc1[4];     // [group i] -> cols tc*4+64i .. +3
#pragma unroll
    for (int i = 0; i < 4; i++) {
        acc0[i] = make_float4(0.f, 0.f, 0.f, 0.f);
        acc1[i] = make_float4(0.f, 0.f, 0.f, 0.f);
    }

#pragma unroll 1
    for (int k = 0; k < F_IN; k++) {
        float a0 = xs[r0][k], a1 = xs[r1][k];
        const float* wrow = &W1s[k * C1 + tc * 4];
#pragma unroll
        for (int i = 0; i < 4; i++) {
            float4 b = *(const float4*)&wrow[64 * i];
            acc0[i].x += a0 * b.x; acc0[i].y += a0 * b.y;
            acc0[i].z += a0 * b.z; acc0[i].w += a0 * b.w;
            acc1[i].x += a1 * b.x; acc1[i].y += a1 * b.y;
            acc1[i].z += a1 * b.z; acc1[i].w += a1 * b.w;
        }
    }

    int node0 = n0 + r0, node1 = n0 + r1;
    // logits + fp16 stores (groups i<2 -> head0, i>=2 -> head1)
    float s0h0 = 0.f, s0h1 = 0.f, d0h0 = 0.f, d0h1 = 0.f;
    float s1h0 = 0.f, s1h1 = 0.f, d1h0 = 0.f, d1h1 = 0.f;
#pragma unroll
    for (int i = 0; i < 4; i++) {
        int cb = tc * 4 + 64 * i;
        float4 as = *(const float4*)&a_s[cb];
        float4 ad = *(const float4*)&a_d[cb];
        float p0s = acc0[i].x * as.x + acc0[i].y * as.y + acc0[i].z * as.z + acc0[i].w * as.w;
        float p0d = acc0[i].x * ad.x + acc0[i].y * ad.y + acc0[i].z * ad.z + acc0[i].w * ad.w;
        float p1s = acc1[i].x * as.x + acc1[i].y * as.y + acc1[i].z * as.z + acc1[i].w * as.w;
        float p1d = acc1[i].x * ad.x + acc1[i].y * ad.y + acc1[i].z * ad.z + acc1[i].w * ad.w;
        if (i < 2) { s0h0 += p0s; d0h0 += p0d; s1h0 += p1s; d1h0 += p1d; }
        else       { s0h1 += p0s; d0h1 += p0d; s1h1 += p1s; d1h1 += p1d; }
        __half2 h0a = __floats2half2_rn(acc0[i].x, acc0[i].y);
        __half2 h0b = __floats2half2_rn(acc0[i].z, acc0[i].w);
        __half2 h1a = __floats2half2_rn(acc1[i].x, acc1[i].y);
        __half2 h1b = __floats2half2_rn(acc1[i].z, acc1[i].w);
        if (node0 < N_NODES) {
            uint2 p; p.x = *(unsigned*)&h0a; p.y = *(unsigned*)&h0b;
            *(uint2*)&g_h1h[node0 * C1 + cb] = p;
        }
        if (node1 < N_NODES) {
            uint2 p; p.x = *(unsigned*)&h1a; p.y = *(unsigned*)&h1b;
            *(uint2*)&g_h1h[node1 * C1 + cb] = p;
        }
    }
    // reduce across the 16 tc lanes (xor <= 8 stays in each 16-lane group)
#pragma unroll
    for (int o = 8; o > 0; o >>= 1) {
        s0h0 += __shfl_xor_sync(0xFFFFFFFFu, s0h0, o);
        s0h1 += __shfl_xor_sync(0xFFFFFFFFu, s0h1, o);
        d0h0 += __shfl_xor_sync(0xFFFFFFFFu, d0h0, o);
        d0h1 += __shfl_xor_sync(0xFFFFFFFFu, d0h1, o);
        s1h0 += __shfl_xor_sync(0xFFFFFFFFu, s1h0, o);
        s1h1 += __shfl_xor_sync(0xFFFFFFFFu, s1h1, o);
        d1h0 += __shfl_xor_sync(0xFFFFFFFFu, d1h0, o);
        d1h1 += __shfl_xor_sync(0xFFFFFFFFu, d1h1, o);
    }
    if (tc == 0) {
        if (node0 < N_NODES) {
            g_al_s1[node0 * 2]     = s0h0;  g_al_s1[node0 * 2 + 1] = s0h1;
            g_al_d1[node0 * 2]     = d0h0;  g_al_d1[node0 * 2 + 1] = d0h1;
        }
        if (node1 < N_NODES) {
            g_al_s1[node1 * 2]     = s1h0;  g_al_s1[node1 * 2 + 1] = s1h1;
            g_al_d1[node1 * 2]     = d1h0;  g_al_d1[node1 * 2 + 1] = d1h1;
        }
    }
}

// ---------------- layer 1 fused softmax+gather (weights hoisted) + al2 epilogue ----------------
__global__ void k_gat1(const float* __restrict__ b1) {
    int n = blockIdx.x * 8 + (threadIdx.x >> 5);
    int lane = threadIdx.x & 31;
    if (n >= N_NODES) return;
    int row = g_rowstart[n], end = g_rowstart[n + 1];
    int h = lane >> 4;
    float alD0 = g_al_d1[n * 2], alD1 = g_al_d1[n * 2 + 1];

    float den = 0.f;
    float acc[8] = {0.f, 0.f, 0.f, 0.f, 0.f, 0.f, 0.f, 0.f};
    for (int j0 = row; j0 < end; j0 += 32) {
        int idx = j0 + lane;
        bool valid = idx < end;
        int sj = valid ? __ldg(&g_csrc[idx]) : 0;
        float w0l = 0.f, w1l = 0.f;
        if (valid) {
            float as0 = __ldg(&g_al_s1[sj * 2]);
            float as1 = __ldg(&g_al_s1[sj * 2 + 1]);
            w0l = __expf(lrelu(as0 + alD0));
            w1l = __expf(lrelu(as1 + alD1));
        }
        int cnt = min(32, end - j0);
        int k = 0;
        for (; k + 1 < cnt; k += 2) {
            int s0 = __shfl_sync(0xFFFFFFFFu, sj, k);
            int s1 = __shfl_sync(0xFFFFFFFFu, sj, k + 1);
            float w0a = __shfl_sync(0xFFFFFFFFu, w0l, k);
            float w1a = __shfl_sync(0xFFFFFFFFu, w1l, k);
            float w0b = __shfl_sync(0xFFFFFFFFu, w0l, k + 1);
            float w1b = __shfl_sync(0xFFFFFFFFu, w1l, k + 1);
            uint4 r0 = *(const uint4*)&g_h1h[s0 * C1 + lane * 8];
            uint4 r1 = *(const uint4*)&g_h1h[s1 * C1 + lane * 8];
            float wA = h ? w1a : w0a;
            float wB = h ? w1b : w0b;
            den += wA + wB;
            fma8h(acc, r0, wA);
            fma8h(acc, r1, wB);
        }
        if (k < cnt) {
            int s = __shfl_sync(0xFFFFFFFFu, sj, k);
            float w0a = __shfl_sync(0xFFFFFFFFu, w0l, k);
            float w1a = __shfl_sync(0xFFFFFFFFu, w1l, k);
            float wA = h ? w1a : w0a;
            den += wA;
            fma8h(acc, *(const uint4*)&g_h1h[s * C1 + lane * 8], wA);
        }
    }
    float inv = 1.f / (den + 1e-16f);
    int c0 = lane * 8;
    float4 o0, o1;
    o0.x = fmaxf(acc[0] * inv + b1[c0 + 0], 0.f);
    o0.y = fmaxf(acc[1] * inv + b1[c0 + 1], 0.f);
    o0.z = fmaxf(acc[2] * inv + b1[c0 + 2], 0.f);
    o0.w = fmaxf(acc[3] * inv + b1[c0 + 3], 0.f);
    o1.x = fmaxf(acc[4] * inv + b1[c0 + 4], 0.f);
    o1.y = fmaxf(acc[5] * inv + b1[c0 + 5], 0.f);
    o1.z = fmaxf(acc[6] * inv + b1[c0 + 6], 0.f);
    o1.w = fmaxf(acc[7] * inv + b1[c0 + 7], 0.f);
    *(float4*)&g_out1[n * C1 + c0] = o0;
    *(float4*)&g_out1[n * C1 + c0 + 4] = o1;

    // fused al2: al_s2[n] = relu(out1[n]) . (W2 @ as2)  (likewise d)
    float4 ws0 = *(const float4*)&g_wvs[c0], ws1 = *(const float4*)&g_wvs[c0 + 4];
    float4 wd0 = *(const float4*)&g_wvd[c0], wd1 = *(const float4*)&g_wvd[c0 + 4];
    float ps = o0.x * ws0.x + o0.y * ws0.y + o0.z * ws0.z + o0.w * ws0.w
             + o1.x * ws1.x + o1.y * ws1.y + o1.z * ws1.z + o1.w * ws1.w;
    float pd = o0.x * wd0.x + o0.y * wd0.y + o0.z * wd0.z + o0.w * wd0.w
             + o1.x * wd1.x + o1.y * wd1.y + o1.z * wd1.z + o1.w * wd1.w;
#pragma unroll
    for (int o = 16; o > 0; o >>= 1) {
        ps += __shfl_xor_sync(0xFFFFFFFFu, ps, o);
        pd += __shfl_xor_sync(0xFFFFFFFFu, pd, o);
    }
    if (lane == 0) { g_al_s2[n] = ps; g_al_d2[n] = pd; }
}

// ---------------- tf32 tensor-core GEMM, fp16 output: g_h2h = g_out1 @ W2 ----------------
#define TCM 128
#define TCN 128
#define TCK 32
__global__ void __launch_bounds__(256) k_gemm2(const float* __restrict__ A,
                                               const float* __restrict__ B,
                                               __half* __restrict__ C) {
    __shared__ __align__(16) float As[TCM][TCK + 4];   // 18.4 KB
    __shared__ __align__(16) float Bs[TCK][TCN + 4];   // 16.9 KB
    __shared__ __align__(16) float Epi[8][256];        // 8 KB: per-warp 16x16 patch
    int tid = threadIdx.x;
    int bm = blockIdx.x * TCM, bn = blockIdx.y * TCN;
    int wid = tid >> 5, lane = tid & 31;
    int warp_m = (wid >> 1) * 32, warp_n = (wid & 1) * 64;

    wmma::fragment<wmma::accumulator, 16, 16, 8, float> c_frag[2][4];
#pragma unroll
    for (int i = 0; i < 2; i++)
#pragma unroll
        for (int j = 0; j < 4; j++) wmma::fill_fragment(c_frag[i][j], 0.f);

    for (int k0 = 0; k0 < 256; k0 += TCK) {
#pragma unroll
        for (int p = 0; p < 4; p++) {
            int r = (tid >> 3) + p * 32;
            int c4 = tid & 7;
            float4 v = *(const float4*)&A[(size_t)(bm + r) * 256 + k0 + c4 * 4];
            *(float4*)&As[r][c4 * 4] = v;
        }
#pragma unroll
        for (int p = 0; p < 4; p++) {
            int r = (tid >> 5) + p * 8;
            int c4 = tid & 31;
            float4 v = *(const float4*)&B[(size_t)(k0 + r) * 256 + bn + c4 * 4];
            *(float4*)&Bs[r][c4 * 4] = v;
        }
        __syncthreads();

#pragma unroll
        for (int kk = 0; kk < TCK; kk += 8) {
            wmma::fragment<wmma::matrix_a, 16, 16, 8, wmma::precision::tf32, wmma::row_major> a_frag[2];
            wmma::fragment<wmma::matrix_b, 16, 16, 8, wmma::precision::tf32, wmma::row_major> b_frag[4];
#pragma unroll
            for (int i = 0; i < 2; i++) {
                wmma::load_matrix_sync(a_frag[i], &As[warp_m + i * 16][kk], TCK + 4);
#pragma unroll
                for (int t = 0; t < a_frag[i].num_elements; t++)
                    a_frag[i].x[t] = wmma::__float_to_tf32(a_frag[i].x[t]);
            }
#pragma unroll
            for (int j = 0; j < 4; j++) {
                wmma::load_matrix_sync(b_frag[j], &Bs[kk][warp_n + j * 16], TCN + 4);
#pragma unroll
                for (int t = 0; t < b_frag[j].num_elements; t++)
                    b_frag[j].x[t] = wmma::__float_to_tf32(b_frag[j].x[t]);
            }
#pragma unroll
            for (int i = 0; i < 2; i++)
#pragma unroll
                for (int j = 0; j < 4; j++)
                    wmma::mma_sync(c_frag[i][j], a_frag[i], b_frag[j], c_frag[i][j]);
        }
        __syncthreads();
    }

    // epilogue: stage each 16x16 fragment through smem, convert to fp16, store
    float* patch = &Epi[wid][0];
    int er = lane >> 1, ec = (lane & 1) * 8;   // each lane: 8 floats of one row
#pragma unroll
    for (int i = 0; i < 2; i++)
#pragma unroll
        for (int j = 0; j < 4; j++) {
            wmma::store_matrix_sync(patch, c_frag[i][j], 16, wmma::mem_row_major);
            __syncwarp();
            float4 a = *(float4*)&patch[er * 16 + ec];
            float4 b = *(float4*)&patch[er * 16 + ec + 4];
            __half2 hh[4];
            hh[0] = __floats2half2_rn(a.x, a.y);
            hh[1] = __floats2half2_rn(a.z, a.w);
            hh[2] = __floats2half2_rn(b.x, b.y);
            hh[3] = __floats2half2_rn(b.z, b.w);
            size_t off = (size_t)(bm + warp_m + i * 16 + er) * 256 + bn + warp_n + j * 16 + ec;
            *(uint4*)&C[off] = *(uint4*)hh;
            __syncwarp();
        }
}

// ---------------- layer 2 fused softmax+gather (weights hoisted) + bias/relu + pool ----------------
__global__ void k_gat2(const float* __restrict__ b2, const int* __restrict__ batch) {
    int n = blockIdx.x * 8 + (threadIdx.x >> 5);
    int lane = threadIdx.x & 31;
    if (n >= N_NODES) return;
    int row = g_rowstart[n], end = g_rowstart[n + 1];
    float alD = g_al_d2[n];

    float den = 0.f;
    float acc[8] = {0.f, 0.f, 0.f, 0.f, 0.f, 0.f, 0.f, 0.f};
    for (int j0 = row; j0 < end; j0 += 32) {
        int idx = j0 + lane;
        bool valid = idx < end;
        int sj = valid ? __ldg(&g_csrc[idx]) : 0;
        float wl = valid ? __expf(lrelu(__ldg(&g_al_s2[sj]) + alD)) : 0.f;
        int cnt = min(32, end - j0);
        int k = 0;
        for (; k + 1 < cnt; k += 2) {
            int s0 = __shfl_sync(0xFFFFFFFFu, sj, k);
            int s1 = __shfl_sync(0xFFFFFFFFu, sj, k + 1);
            float w0 = __shfl_sync(0xFFFFFFFFu, wl, k);
            float w1 = __shfl_sync(0xFFFFFFFFu, wl, k + 1);
            uint4 r0 = *(const uint4*)&g_h2h[s0 * C2 + lane * 8];
            uint4 r1 = *(const uint4*)&g_h2h[s1 * C2 + lane * 8];
            den += w0 + w1;
            fma8h(acc, r0, w0);
            fma8h(acc, r1, w1);
        }
        if (k < cnt) {
            int s = __shfl_sync(0xFFFFFFFFu, sj, k);
            float w = __shfl_sync(0xFFFFFFFFu, wl, k);
            den += w;
            fma8h(acc, *(const uint4*)&g_h2h[s * C2 + lane * 8], w);
        }
    }
    float inv = 1.f / (den + 1e-16f);
    int c0 = lane * 8;
    float4 o0, o1;
    o0.x = fmaxf(acc[0] * inv + b2[c0 + 0], 0.f);
    o0.y = fmaxf(acc[1] * inv + b2[c0 + 1], 0.f);
    o0.z = fmaxf(acc[2] * inv + b2[c0 + 2], 0.f);
    o0.w = fmaxf(acc[3] * inv + b2[c0 + 3], 0.f);
    o1.x = fmaxf(acc[4] * inv + b2[c0 + 4], 0.f);
    o1.y = fmaxf(acc[5] * inv + b2[c0 + 5], 0.f);
    o1.z = fmaxf(acc[6] * inv + b2[c0 + 6], 0.f);
    o1.w = fmaxf(acc[7] * inv + b2[c0 + 7], 0.f);
    int g = batch[n];
    red_add_v4(&g_pool[g * 256 + c0], o0);
    red_add_v4(&g_pool[g * 256 + c0 + 4], o1);
    if (lane == 0) atomicAdd(&g_cnt[g], 1.0f);
}

// ---------------- MLP head ----------------
__global__ void k_mlp1(const float* __restrict__ fw, const float* __restrict__ fb) {
    int g = blockIdx.x >> 2, q = blockIdx.x & 3;
    int t = threadIdx.x;
    __shared__ float grow[256];
    float inv = 1.0f / fmaxf(g_cnt[g], 1.0f);
    grow[t] = g_pool[g * 256 + t] * inv;
    __syncthreads();
    int col = q * 256 + t;
    float acc = fb[col];
#pragma unroll 8
    for (int k = 0; k < 256; k++) acc += grow[k] * fw[k * 1024 + col];
    g_fc1[g * 1024 + col] = fmaxf(acc, 0.f);
}

__global__ void k_mlp2(const float* __restrict__ fw, const float* __restrict__ fb,
                       float* __restrict__ out) {
    int g = blockIdx.x;
    int t = threadIdx.x; // 128
    __shared__ float row[1024];
    for (int k = t; k < 1024; k += 128) row[k] = g_fc1[g * 1024 + k];
    __syncthreads();
    float acc = fb[t];
#pragma unroll 8
    for (int k = 0; k < 1024; k++) acc += row[k] * fw[k * 128 + t];
    out[g * 128 + t] = acc;
}

// ---------------- host launcher ----------------
static void* sym(const void* s) {
    void* p = nullptr;
    cudaGetSymbolAddress(&p, s);
    return p;
}

extern "C" void kernel_launch(void* const* d_in, const int* in_sizes, int n_in,
                              void* d_out, int out_size) {
    const float* x      = (const float*)d_in[0];
    const int*   src    = (const int*)d_in[1];
    const int*   dst    = (const int*)d_in[2];
    const int*   batch  = (const int*)d_in[3];
    const float* W1     = (const float*)d_in[4];
    const float* a_src1 = (const float*)d_in[5];
    const float* a_dst1 = (const float*)d_in[6];
    const float* b1     = (const float*)d_in[7];
    const float* W2     = (const float*)d_in[8];
    const float* a_src2 = (const float*)d_in[9];
    const float* a_dst2 = (const float*)d_in[10];
    const float* b2     = (const float*)d_in[11];
    const float* fc1_w  = (const float*)d_in[12];
    const float* fc1_b  = (const float*)d_in[13];
    const float* fc2_w  = (const float*)d_in[14];
    const float* fc2_b  = (const float*)d_in[15];
    float* out = (float*)d_out;

    static bool attr_set = false;
    if (!attr_set) {
        cudaFuncSetAttribute(k_gemm1, cudaFuncAttributeMaxDynamicSharedMemorySize, G1_SMEM);
        attr_set = true;
    }

    cudaMemsetAsync(sym(g_deg), 0, N_NODES * sizeof(int));

    // CSR build (deg fused with wvec + pool zeroing across spare blocks)
    k_deg<<<(NT + 255) / 256, 256>>>(dst, W2, a_src2, a_dst2);
    k_scan<<<1, 1024>>>();
    k_fill<<<(NT + 255) / 256, 256>>>(src, dst);

    // layer 1
    k_gemm1<<<(N_NODES + G1_M - 1) / G1_M, 256, G1_SMEM>>>(x, W1, a_src1, a_dst1);
    k_gat1<<<(N_NODES + 7) / 8, 256>>>(b1);

    // layer 2 (tf32 tensor cores, fp16 output, padded rows)
    float* d_o1 = (float*)sym(g_out1);
    __half* d_h2h = (__half*)sym(g_h2h);
    dim3 g2(N_PAD / TCM, 256 / TCN);
    k_gemm2<<<g2, 256>>>(d_o1, W2, d_h2h);
    k_gat2<<<(N_NODES + 7) / 8, 256>>>(b2, batch);

    // MLP
    k_mlp1<<<N_GRAPHS * 4, 256>>>(fc1_w, fc1_b);
    k_mlp2<<<N_GRAPHS, 128>>>(fc2_w, fc2_b, out);
}

// round 16
// speedup vs baseline: 1.0483x; 1.0044x over previous
#include <cuda_runtime.h>
#include <cuda_bf16.h>
#include <cuda_fp16.h>
#include <mma.h>
using namespace nvcuda;

#define N_NODES 50000
#define N_PAD   50048       // padded to multiple of 128 for the TC GEMM
#define N_EDGES 800000
#define NT      850000      // edges + self loops
#define N_GRAPHS 256
#define F_IN    41
#define C1      256
#define C2      256
#define NEG_SLOPE 0.2f

// ---------------- scratch (device globals) ----------------
__device__ __align__(16) __half g_h1h[N_NODES * C1];   // h1, fp16 (only gat1 reads)
__device__ float g_al_s1[N_NODES * 2];
__device__ float g_al_d1[N_NODES * 2];
__device__ __align__(16) float g_out1[N_PAD * C1];     // pad rows stay zero
__device__ __align__(16) __half g_h2h[N_PAD * C2];     // h2, fp16 (gemm2 writes, gat2 reads)
__device__ float g_al_s2[N_NODES];
__device__ float g_al_d2[N_NODES];
__device__ __align__(16) float g_wvs[C2];
__device__ __align__(16) float g_wvd[C2];
__device__ __align__(16) float g_pool[N_GRAPHS * 256];
__device__ float g_cnt[N_GRAPHS];
__device__ float g_fc1[N_GRAPHS * 1024];
// CSR
__device__ int g_deg[N_NODES];
__device__ int g_rowstart[N_NODES + 1];
__device__ int g_cursor[N_NODES];
__device__ int g_csrc[NT];

__device__ __forceinline__ void red_add_v4(float* addr, float4 v) {
    asm volatile("red.global.add.v4.f32 [%0], {%1, %2, %3, %4};"
                 :: "l"(addr), "f"(v.x), "f"(v.y), "f"(v.z), "f"(v.w)
                 : "memory");
}
__device__ __forceinline__ float lrelu(float e) { return e > 0.f ? e : NEG_SLOPE * e; }

// unpack 8 halves (uint4) and FMA into acc with weight w
__device__ __forceinline__ void fma8h(float* acc, uint4 raw, float w) {
    __half2 hh[4];
    *(uint4*)hh = raw;
    float2 p0 = __half22float2(hh[0]);
    float2 p1 = __half22float2(hh[1]);
    float2 p2 = __half22float2(hh[2]);
    float2 p3 = __half22float2(hh[3]);
    acc[0] += w * p0.x; acc[1] += w * p0.y;
    acc[2] += w * p1.x; acc[3] += w * p1.y;
    acc[4] += w * p2.x; acc[5] += w * p2.y;
    acc[6] += w * p3.x; acc[7] += w * p3.y;
}

// single-block exclusive scan over g_deg -> g_rowstart, g_cursor
__global__ void k_scan() {
    __shared__ int warp_sums[32];
    __shared__ int s_carry;
    int tid = threadIdx.x, lane = tid & 31, w = tid >> 5;
    if (tid == 0) s_carry = 0;
    __syncthreads();
    for (int base = 0; base < N_NODES; base += 1024) {
        int i = base + tid;
        int v = (i < N_NODES) ? g_deg[i] : 0;
        int incl = v;
#pragma unroll
        for (int o = 1; o < 32; o <<= 1) {
            int t = __shfl_up_sync(0xFFFFFFFFu, incl, o);
            if (lane >= o) incl += t;
        }
        if (lane == 31) warp_sums[w] = incl;
        __syncthreads();
        if (w == 0) {
            int s = warp_sums[lane];
#pragma unroll
            for (int o = 1; o < 32; o <<= 1) {
                int t = __shfl_up_sync(0xFFFFFFFFu, s, o);
                if (lane >= o) s += t;
            }
            warp_sums[lane] = s;    // inclusive over warps
        }
        __syncthreads();
        int warp_off = (w == 0) ? 0 : warp_sums[w - 1];
        int excl = s_carry + warp_off + incl - v;
        if (i < N_NODES) { g_rowstart[i] = excl; g_cursor[i] = excl; }
        __syncthreads();
        if (tid == 0) s_carry += warp_sums[31];
        __syncthreads();
    }
    if (tid == 0) g_rowstart[N_NODES] = NT;
}

__global__ void k_fill(const int* __restrict__ src, const int* __restrict__ dst) {
    int i = blockIdx.x * blockDim.x + threadIdx.x;
    if (i >= NT) return;
    int s, d;
    if (i < N_EDGES) { s = src[i]; d = dst[i]; } else { s = d = i - N_EDGES; }
    int p = atomicAdd(&g_cursor[d], 1);
    g_csrc[p] = s;
}

// ---------------- layer 1 tiled GEMM + attention logits + fused deg/wvec/pool-zero ----------------
// 32 nodes per 256-thread block; thread (tr,tc): rows tr*2..+1, cols {tc*4+64i ..+3}.
// Prologue (independent work, overlaps the GEMM): grid-stride degree histogram;
// blocks 0-31 compute wvec rows; blocks 32-95 zero g_pool; block 96 zeros g_cnt.
#define G1_M 32
#define G1_SMEM (F_IN * C1 * 4 + G1_M * 43 * 4)
__global__ void __launch_bounds__(256) k_gemm1(const float* __restrict__ x,
                                               const float* __restrict__ W1,
                                               const float* __restrict__ a_s,
                                               const float* __restrict__ a_d,
                                               const int* __restrict__ dst,
                                               const float* __restrict__ W2,
                                               const float* __restrict__ as2,
                                               const float* __restrict__ ad2) {
    extern __shared__ float sm[];
    float* W1s = sm;                                  // F_IN*C1
    float (*xs)[43] = (float (*)[43])(sm + F_IN * C1);
    int tid = threadIdx.x;
    int n0 = blockIdx.x * G1_M;

    // ---- fused degree histogram (grid-stride over NT edges) ----
    for (int e = blockIdx.x * blockDim.x + tid; e < NT; e += gridDim.x * blockDim.x) {
        int d = (e < N_EDGES) ? dst[e] : e - N_EDGES;
        atomicAdd(&g_deg[d], 1);
    }
    // ---- fused wvec / pool zeroing on low blocks ----
    if (blockIdx.x < 32) {
        int k = blockIdx.x * 8 + (tid >> 5);
        int lane = tid & 31;
        float s = 0.f, d = 0.f;
#pragma unroll
        for (int j = lane; j < 256; j += 32) {
            float wv = W2[k * 256 + j];
            s += wv * as2[j];
            d += wv * ad2[j];
        }
#pragma unroll
        for (int o = 16; o > 0; o >>= 1) {
            s += __shfl_xor_sync(0xFFFFFFFFu, s, o);
            d += __shfl_xor_sync(0xFFFFFFFFu, d, o);
        }
        if (lane == 0) { g_wvs[k] = s; g_wvd[k] = d; }
    } else if (blockIdx.x < 96) {
        int idx = (blockIdx.x - 32) * 256 + tid;
        ((float4*)g_pool)[idx] = make_float4(0.f, 0.f, 0.f, 0.f);
    } else if (blockIdx.x == 96) {
        if (tid < N_GRAPHS) g_cnt[tid] = 0.f;
    }

    // ---- GEMM ----
    for (int idx = tid; idx < (F_IN * C1) / 4; idx += 256)
        ((float4*)W1s)[idx] = ((const float4*)W1)[idx];
    for (int idx = tid; idx < G1_M * F_IN; idx += 256) {
        int r = idx / F_IN, c = idx % F_IN;
        int node = n0 + r;
        xs[r][c] = (node < N_NODES) ? x[node * F_IN + c] : 0.f;
    }
    __syncthreads();

    int tr = tid >> 4, tc = tid & 15;
    int r0 = tr * 2, r1 = r0 + 1;
    float4 acc0[4], acc1[4];     // [group i] -> cols tc*4+64i .. +3
#pragma unroll
    for (int i = 0; i < 4; i++) {
        acc0[i] = make_float4(0.f, 0.f, 0.f, 0.f);
        acc1[i] = make_float4(0.f, 0.f, 0.f, 0.f);
    }

#pragma unroll 1
    for (int k = 0; k < F_IN; k++) {
        float a0 = xs[r0][k], a1 = xs[r1][k];
        const float* wrow = &W1s[k * C1 + tc * 4];
#pragma unroll
        for (int i = 0; i < 4; i++) {
            float4 b = *(const float4*)&wrow[64 * i];
            acc0[i].x += a0 * b.x; acc0[i].y += a0 * b.y;
            acc0[i].z += a0 * b.z; acc0[i].w += a0 * b.w;
            acc1[i].x += a1 * b.x; acc1[i].y += a1 * b.y;
            acc1[i].z += a1 * b.z; acc1[i].w += a1 * b.w;
        }
    }

    int node0 = n0 + r0, node1 = n0 + r1;
    // logits + fp16 stores (groups i<2 -> head0, i>=2 -> head1)
    float s0h0 = 0.f, s0h1 = 0.f, d0h0 = 0.f, d0h1 = 0.f;
    float s1h0 = 0.f, s1h1 = 0.f, d1h0 = 0.f, d1h1 = 0.f;
#pragma unroll
    for (int i = 0; i < 4; i++) {
        int cb = tc * 4 + 64 * i;
        float4 as = *(const float4*)&a_s[cb];
        float4 ad = *(const float4*)&a_d[cb];
        float p0s = acc0[i].x * as.x + acc0[i].y * as.y + acc0[i].z * as.z + acc0[i].w * as.w;
        float p0d = acc0[i].x * ad.x + acc0[i].y * ad.y + acc0[i].z * ad.z + acc0[i].w * ad.w;
        float p1s = acc1[i].x * as.x + acc1[i].y * as.y + acc1[i].z * as.z + acc1[i].w * as.w;
        float p1d = acc1[i].x * ad.x + acc1[i].y * ad.y + acc1[i].z * ad.z + acc1[i].w * ad.w;
        if (i < 2) { s0h0 += p0s; d0h0 += p0d; s1h0 += p1s; d1h0 += p1d; }
        else       { s0h1 += p0s; d0h1 += p0d; s1h1 += p1s; d1h1 += p1d; }
        __half2 h0a = __floats2half2_rn(acc0[i].x, acc0[i].y);
        __half2 h0b = __floats2half2_rn(acc0[i].z, acc0[i].w);
        __half2 h1a = __floats2half2_rn(acc1[i].x, acc1[i].y);
        __half2 h1b = __floats2half2_rn(acc1[i].z, acc1[i].w);
        if (node0 < N_NODES) {
            uint2 p; p.x = *(unsigned*)&h0a; p.y = *(unsigned*)&h0b;
            *(uint2*)&g_h1h[node0 * C1 + cb] = p;
        }
        if (node1 < N_NODES) {
            uint2 p; p.x = *(unsigned*)&h1a; p.y = *(unsigned*)&h1b;
            *(uint2*)&g_h1h[node1 * C1 + cb] = p;
        }
    }
    // reduce across the 16 tc lanes (xor <= 8 stays in each 16-lane group)
#pragma unroll
    for (int o = 8; o > 0; o >>= 1) {
        s0h0 += __shfl_xor_sync(0xFFFFFFFFu, s0h0, o);
        s0h1 += __shfl_xor_sync(0xFFFFFFFFu, s0h1, o);
        d0h0 += __shfl_xor_sync(0xFFFFFFFFu, d0h0, o);
        d0h1 += __shfl_xor_sync(0xFFFFFFFFu, d0h1, o);
        s1h0 += __shfl_xor_sync(0xFFFFFFFFu, s1h0, o);
        s1h1 += __shfl_xor_sync(0xFFFFFFFFu, s1h1, o);
        d1h0 += __shfl_xor_sync(0xFFFFFFFFu, d1h0, o);
        d1h1 += __shfl_xor_sync(0xFFFFFFFFu, d1h1, o);
    }
    if (tc == 0) {
        if (node0 < N_NODES) {
            g_al_s1[node0 * 2]     = s0h0;  g_al_s1[node0 * 2 + 1] = s0h1;
            g_al_d1[node0 * 2]     = d0h0;  g_al_d1[node0 * 2 + 1] = d0h1;
        }
        if (node1 < N_NODES) {
            g_al_s1[node1 * 2]     = s1h0;  g_al_s1[node1 * 2 + 1] = s1h1;
            g_al_d1[node1 * 2]     = d1h0;  g_al_d1[node1 * 2 + 1] = d1h1;
        }
    }
}

// ---------------- layer 1 fused softmax+gather (weights hoisted) + al2 epilogue ----------------
__global__ void k_gat1(const float* __restrict__ b1) {
    int n = blockIdx.x * 8 + (threadIdx.x >> 5);
    int lane = threadIdx.x & 31;
    if (n >= N_NODES) return;
    int row = g_rowstart[n], end = g_rowstart[n + 1];
    int h = lane >> 4;
    float alD0 = g_al_d1[n * 2], alD1 = g_al_d1[n * 2 + 1];

    float den = 0.f;
    float acc[8] = {0.f, 0.f, 0.f, 0.f, 0.f, 0.f, 0.f, 0.f};
    for (int j0 = row; j0 < end; j0 += 32) {
        int idx = j0 + lane;
        bool valid = idx < end;
        int sj = valid ? __ldg(&g_csrc[idx]) : 0;
        float w0l = 0.f, w1l = 0.f;
        if (valid) {
            float as0 = __ldg(&g_al_s1[sj * 2]);
            float as1 = __ldg(&g_al_s1[sj * 2 + 1]);
            w0l = __expf(lrelu(as0 + alD0));
            w1l = __expf(lrelu(as1 + alD1));
        }
        int cnt = min(32, end - j0);
        int k = 0;
        for (; k + 1 < cnt; k += 2) {
            int s0 = __shfl_sync(0xFFFFFFFFu, sj, k);
            int s1 = __shfl_sync(0xFFFFFFFFu, sj, k + 1);
            float w0a = __shfl_sync(0xFFFFFFFFu, w0l, k);
            float w1a = __shfl_sync(0xFFFFFFFFu, w1l, k);
            float w0b = __shfl_sync(0xFFFFFFFFu, w0l, k + 1);
            float w1b = __shfl_sync(0xFFFFFFFFu, w1l, k + 1);
            uint4 r0 = *(const uint4*)&g_h1h[s0 * C1 + lane * 8];
            uint4 r1 = *(const uint4*)&g_h1h[s1 * C1 + lane * 8];
            float wA = h ? w1a : w0a;
            float wB = h ? w1b : w0b;
            den += wA + wB;
            fma8h(acc, r0, wA);
            fma8h(acc, r1, wB);
        }
        if (k < cnt) {
            int s = __shfl_sync(0xFFFFFFFFu, sj, k);
            float w0a = __shfl_sync(0xFFFFFFFFu, w0l, k);
            float w1a = __shfl_sync(0xFFFFFFFFu, w1l, k);
            float wA = h ? w1a : w0a;
            den += wA;
            fma8h(acc, *(const uint4*)&g_h1h[s * C1 + lane * 8], wA);
        }
    }
    float inv = 1.f / (den + 1e-16f);
    int c0 = lane * 8;
    float4 o0, o1;
    o0.x = fmaxf(acc[0] * inv + b1[c0 + 0], 0.f);
    o0.y = fmaxf(acc[1] * inv + b1[c0 + 1], 0.f);
    o0.z = fmaxf(acc[2] * inv + b1[c0 + 2], 0.f);
    o0.w = fmaxf(acc[3] * inv + b1[c0 + 3], 0.f);
    o1.x = fmaxf(acc[4] * inv + b1[c0 + 4], 0.f);
    o1.y = fmaxf(acc[5] * inv + b1[c0 + 5], 0.f);
    o1.z = fmaxf(acc[6] * inv + b1[c0 + 6], 0.f);
    o1.w = fmaxf(acc[7] * inv + b1[c0 + 7], 0.f);
    *(float4*)&g_out1[n * C1 + c0] = o0;
    *(float4*)&g_out1[n * C1 + c0 + 4] = o1;

    // fused al2: al_s2[n] = relu(out1[n]) . (W2 @ as2)  (likewise d)
    float4 ws0 = *(const float4*)&g_wvs[c0], ws1 = *(const float4*)&g_wvs[c0 + 4];
    float4 wd0 = *(const float4*)&g_wvd[c0], wd1 = *(const float4*)&g_wvd[c0 + 4];
    float ps = o0.x * ws0.x + o0.y * ws0.y + o0.z * ws0.z + o0.w * ws0.w
             + o1.x * ws1.x + o1.y * ws1.y + o1.z * ws1.z + o1.w * ws1.w;
    float pd = o0.x * wd0.x + o0.y * wd0.y + o0.z * wd0.z + o0.w * wd0.w
             + o1.x * wd1.x + o1.y * wd1.y + o1.z * wd1.z + o1.w * wd1.w;
#pragma unroll
    for (int o = 16; o > 0; o >>= 1) {
        ps += __shfl_xor_sync(0xFFFFFFFFu, ps, o);
        pd += __shfl_xor_sync(0xFFFFFFFFu, pd, o);
    }
    if (lane == 0) { g_al_s2[n] = ps; g_al_d2[n] = pd; }
}

// ---------------- tf32 tensor-core GEMM, fp16 output: g_h2h = g_out1 @ W2 ----------------
#define TCM 128
#define TCN 128
#define TCK 32
__global__ void __launch_bounds__(256) k_gemm2(const float* __restrict__ A,
                                               const float* __restrict__ B,
                                               __half* __restrict__ C) {
    __shared__ __align__(16) float As[TCM][TCK + 4];   // 18.4 KB
    __shared__ __align__(16) float Bs[TCK][TCN + 4];   // 16.9 KB
    __shared__ __align__(16) float Epi[8][256];        // 8 KB: per-warp 16x16 patch
    int tid = threadIdx.x;
    int bm = blockIdx.x * TCM, bn = blockIdx.y * TCN;
    int wid = tid >> 5, lane = tid & 31;
    int warp_m = (wid >> 1) * 32, warp_n = (wid & 1) * 64;

    wmma::fragment<wmma::accumulator, 16, 16, 8, float> c_frag[2][4];
#pragma unroll
    for (int i = 0; i < 2; i++)
#pragma unroll
        for (int j = 0; j < 4; j++) wmma::fill_fragment(c_frag[i][j], 0.f);

    for (int k0 = 0; k0 < 256; k0 += TCK) {
#pragma unroll
        for (int p = 0; p < 4; p++) {
            int r = (tid >> 3) + p * 32;
            int c4 = tid & 7;
            float4 v = *(const float4*)&A[(size_t)(bm + r) * 256 + k0 + c4 * 4];
            *(float4*)&As[r][c4 * 4] = v;
        }
#pragma unroll
        for (int p = 0; p < 4; p++) {
            int r = (tid >> 5) + p * 8;
            int c4 = tid & 31;
            float4 v = *(const float4*)&B[(size_t)(k0 + r) * 256 + bn + c4 * 4];
            *(float4*)&Bs[r][c4 * 4] = v;
        }
        __syncthreads();

#pragma unroll
        for (int kk = 0; kk < TCK; kk += 8) {
            wmma::fragment<wmma::matrix_a, 16, 16, 8, wmma::precision::tf32, wmma::row_major> a_frag[2];
            wmma::fragment<wmma::matrix_b, 16, 16, 8, wmma::precision::tf32, wmma::row_major> b_frag[4];
#pragma unroll
            for (int i = 0; i < 2; i++) {
                wmma::load_matrix_sync(a_frag[i], &As[warp_m + i * 16][kk], TCK + 4);
#pragma unroll
                for (int t = 0; t < a_frag[i].num_elements; t++)
                    a_frag[i].x[t] = wmma::__float_to_tf32(a_frag[i].x[t]);
            }
#pragma unroll
            for (int j = 0; j < 4; j++) {
                wmma::load_matrix_sync(b_frag[j], &Bs[kk][warp_n + j * 16], TCN + 4);
#pragma unroll
                for (int t = 0; t < b_frag[j].num_elements; t++)
                    b_frag[j].x[t] = wmma::__float_to_tf32(b_frag[j].x[t]);
            }
#pragma unroll
            for (int i = 0; i < 2; i++)
#pragma unroll
                for (int j = 0; j < 4; j++)
                    wmma::mma_sync(c_frag[i][j], a_frag[i], b_frag[j], c_frag[i][j]);
        }
        __syncthreads();
    }

    // epilogue: stage each 16x16 fragment through smem, convert to fp16, store
    float* patch = &Epi[wid][0];
    int er = lane >> 1, ec = (lane & 1) * 8;   // each lane: 8 floats of one row
#pragma unroll
    for (int i = 0; i < 2; i++)
#pragma unroll
        for (int j = 0; j < 4; j++) {
            wmma::store_matrix_sync(patch, c_frag[i][j], 16, wmma::mem_row_major);
            __syncwarp();
            float4 a = *(float4*)&patch[er * 16 + ec];
            float4 b = *(float4*)&patch[er * 16 + ec + 4];
            __half2 hh[4];
            hh[0] = __floats2half2_rn(a.x, a.y);
            hh[1] = __floats2half2_rn(a.z, a.w);
            hh[2] = __floats2half2_rn(b.x, b.y);
            hh[3] = __floats2half2_rn(b.z, b.w);
            size_t off = (size_t)(bm + warp_m + i * 16 + er) * 256 + bn + warp_n + j * 16 + ec;
            *(uint4*)&C[off] = *(uint4*)hh;
            __syncwarp();
        }
}

// ---------------- layer 2 fused softmax+gather (weights hoisted) + bias/relu + pool ----------------
__global__ void k_gat2(const float* __restrict__ b2, const int* __restrict__ batch) {
    int n = blockIdx.x * 8 + (threadIdx.x >> 5);
    int lane = threadIdx.x & 31;
    if (n >= N_NODES) return;
    int row = g_rowstart[n], end = g_rowstart[n + 1];
    float alD = g_al_d2[n];

    float den = 0.f;
    float acc[8] = {0.f, 0.f, 0.f, 0.f, 0.f, 0.f, 0.f, 0.f};
    for (int j0 = row; j0 < end; j0 += 32) {
        int idx = j0 + lane;
        bool valid = idx < end;
        int sj = valid ? __ldg(&g_csrc[idx]) : 0;
        float wl = valid ? __expf(lrelu(__ldg(&g_al_s2[sj]) + alD)) : 0.f;
        int cnt = min(32, end - j0);
        int k = 0;
        for (; k + 1 < cnt; k += 2) {
            int s0 = __shfl_sync(0xFFFFFFFFu, sj, k);
            int s1 = __shfl_sync(0xFFFFFFFFu, sj, k + 1);
            float w0 = __shfl_sync(0xFFFFFFFFu, wl, k);
            float w1 = __shfl_sync(0xFFFFFFFFu, wl, k + 1);
            uint4 r0 = *(const uint4*)&g_h2h[s0 * C2 + lane * 8];
            uint4 r1 = *(const uint4*)&g_h2h[s1 * C2 + lane * 8];
            den += w0 + w1;
            fma8h(acc, r0, w0);
            fma8h(acc, r1, w1);
        }
        if (k < cnt) {
            int s = __shfl_sync(0xFFFFFFFFu, sj, k);
            float w = __shfl_sync(0xFFFFFFFFu, wl, k);
            den += w;
            fma8h(acc, *(const uint4*)&g_h2h[s * C2 + lane * 8], w);
        }
    }
    float inv = 1.f / (den + 1e-16f);
    int c0 = lane * 8;
    float4 o0, o1;
    o0.x = fmaxf(acc[0] * inv + b2[c0 + 0], 0.f);
    o0.y = fmaxf(acc[1] * inv + b2[c0 + 1], 0.f);
    o0.z = fmaxf(acc[2] * inv + b2[c0 + 2], 0.f);
    o0.w = fmaxf(acc[3] * inv + b2[c0 + 3], 0.f);
    o1.x = fmaxf(acc[4] * inv + b2[c0 + 4], 0.f);
    o1.y = fmaxf(acc[5] * inv + b2[c0 + 5], 0.f);
    o1.z = fmaxf(acc[6] * inv + b2[c0 + 6], 0.f);
    o1.w = fmaxf(acc[7] * inv + b2[c0 + 7], 0.f);
    int g = batch[n];
    red_add_v4(&g_pool[g * 256 + c0], o0);
    red_add_v4(&g_pool[g * 256 + c0 + 4], o1);
    if (lane == 0) atomicAdd(&g_cnt[g], 1.0f);
}

// ---------------- MLP head ----------------
__global__ void k_mlp1(const float* __restrict__ fw, const float* __restrict__ fb) {
    int g = blockIdx.x >> 2, q = blockIdx.x & 3;
    int t = threadIdx.x;
    __shared__ float grow[256];
    float inv = 1.0f / fmaxf(g_cnt[g], 1.0f);
    grow[t] = g_pool[g * 256 + t] * inv;
    __syncthreads();
    int col = q * 256 + t;
    float acc = fb[col];
#pragma unroll 8
    for (int k = 0; k < 256; k++) acc += grow[k] * fw[k * 1024 + col];
    g_fc1[g * 1024 + col] = fmaxf(acc, 0.f);
}

__global__ void k_mlp2(const float* __restrict__ fw, const float* __restrict__ fb,
                       float* __restrict__ out) {
    int g = blockIdx.x;
    int t = threadIdx.x; // 128
    __shared__ float row[1024];
    for (int k = t; k < 1024; k += 128) row[k] = g_fc1[g * 1024 + k];
    __syncthreads();
    float acc = fb[t];
#pragma unroll 8
    for (int k = 0; k < 1024; k++) acc += row[k] * fw[k * 128 + t];
    out[g * 128 + t] = acc;
}

// ---------------- host launcher ----------------
static void* sym(const void* s) {
    void* p = nullptr;
    cudaGetSymbolAddress(&p, s);
    return p;
}

extern "C" void kernel_launch(void* const* d_in, const int* in_sizes, int n_in,
                              void* d_out, int out_size) {
    const float* x      = (const float*)d_in[0];
    const int*   src    = (const int*)d_in[1];
    const int*   dst    = (const int*)d_in[2];
    const int*   batch  = (const int*)d_in[3];
    const float* W1     = (const float*)d_in[4];
    const float* a_src1 = (const float*)d_in[5];
    const float* a_dst1 = (const float*)d_in[6];
    const float* b1     = (const float*)d_in[7];
    const float* W2     = (const float*)d_in[8];
    const float* a_src2 = (const float*)d_in[9];
    const float* a_dst2 = (const float*)d_in[10];
    const float* b2     = (const float*)d_in[11];
    const float* fc1_w  = (const float*)d_in[12];
    const float* fc1_b  = (const float*)d_in[13];
    const float* fc2_w  = (const float*)d_in[14];
    const float* fc2_b  = (const float*)d_in[15];
    float* out = (float*)d_out;

    static bool attr_set = false;
    if (!attr_set) {
        cudaFuncSetAttribute(k_gemm1, cudaFuncAttributeMaxDynamicSharedMemorySize, G1_SMEM);
        attr_set = true;
    }

    cudaMemsetAsync(sym(g_deg), 0, N_NODES * sizeof(int));

    // layer-1 GEMM with fused degree histogram / wvec / pool zeroing (launch 1)
    k_gemm1<<<(N_NODES + G1_M - 1) / G1_M, 256, G1_SMEM>>>(x, W1, a_src1, a_dst1,
                                                           dst, W2, a_src2, a_dst2);
    // CSR scan + fill (launches 2, 3)
    k_scan<<<1, 1024>>>();
    k_fill<<<(NT + 255) / 256, 256>>>(src, dst);

    // layer-1 gather (launch 4 -> profiled by ncu)
    k_gat1<<<(N_NODES + 7) / 8, 256>>>(b1);

    // layer 2 (tf32 tensor cores, fp16 output, padded rows)
    float* d_o1 = (float*)sym(g_out1);
    __half* d_h2h = (__half*)sym(g_h2h);
    dim3 g2(N_PAD / TCM, 256 / TCN);
    k_gemm2<<<g2, 256>>>(d_o1, W2, d_h2h);
    k_gat2<<<(N_NODES + 7) / 8, 256>>>(b2, batch);

    // MLP
    k_mlp1<<<N_GRAPHS * 4, 256>>>(fc1_w, fc1_b);
    k_mlp2<<<N_GRAPHS, 128>>>(fc2_w, fc2_b, out);
}

// round 17
// speedup vs baseline: 1.1289x; 1.0769x over previous
#include <cuda_runtime.h>
#include <cuda_bf16.h>
#include <cuda_fp16.h>
#include <mma.h>
using namespace nvcuda;

#define N_NODES 50000
#define N_PAD   50048       // padded to multiple of 128 for the TC GEMM
#define N_EDGES 800000
#define NT      850000      // edges + self loops
#define N_GRAPHS 256
#define F_IN    41
#define C1      256
#define C2      256
#define NEG_SLOPE 0.2f
#define SCAN_BLOCKS ((N_NODES + 1023) / 1024)   // 49

// ---------------- scratch (device globals) ----------------
__device__ __align__(16) __half g_h1h[N_NODES * C1];   // h1, fp16 (only gat1 reads)
__device__ __align__(16) float g_al_s1[N_NODES * 2];
__device__ __align__(16) float g_al_d1[N_NODES * 2];
__device__ __align__(16) float g_out1[N_PAD * C1];     // pad rows stay zero
__device__ __align__(16) __half g_h2h[N_PAD * C2];     // h2, fp16 (gemm2 writes, gat2 reads)
__device__ float g_al_s2[N_NODES];
__device__ float g_al_d2[N_NODES];
__device__ __align__(16) float g_wvs[C2];
__device__ __align__(16) float g_wvd[C2];
__device__ __align__(16) float g_pool[N_GRAPHS * 256];
__device__ float g_cnt[N_GRAPHS];
__device__ float g_fc1[N_GRAPHS * 1024];
// CSR
__device__ int g_deg[N_NODES];
__device__ int g_rowstart[N_NODES + 1];
__device__ int g_cursor[N_NODES];
__device__ int g_csrc[NT];
__device__ int g_blocksum[SCAN_BLOCKS];

__device__ __forceinline__ void red_add_v4(float* addr, float4 v) {
    asm volatile("red.global.add.v4.f32 [%0], {%1, %2, %3, %4};"
                 :: "l"(addr), "f"(v.x), "f"(v.y), "f"(v.z), "f"(v.w)
                 : "memory");
}
__device__ __forceinline__ float lrelu(float e) { return e > 0.f ? e : NEG_SLOPE * e; }

// unpack 8 halves (uint4) and FMA into acc with weight w
__device__ __forceinline__ void fma8h(float* acc, uint4 raw, float w) {
    __half2 hh[4];
    *(uint4*)hh = raw;
    float2 p0 = __half22float2(hh[0]);
    float2 p1 = __half22float2(hh[1]);
    float2 p2 = __half22float2(hh[2]);
    float2 p3 = __half22float2(hh[3]);
    acc[0] += w * p0.x; acc[1] += w * p0.y;
    acc[2] += w * p1.x; acc[3] += w * p1.y;
    acc[4] += w * p2.x; acc[5] += w * p2.y;
    acc[6] += w * p3.x; acc[7] += w * p3.y;
}

// ---------------- parallel CSR scan, phase A: block-local exclusive scan ----------------
__global__ void k_scanA() {
    __shared__ int warp_sums[32];
    int b = blockIdx.x, tid = threadIdx.x, lane = tid & 31, w = tid >> 5;
    int i = b * 1024 + tid;
    int v = (i < N_NODES) ? g_deg[i] : 0;
    int incl = v;
#pragma unroll
    for (int o = 1; o < 32; o <<= 1) {
        int t = __shfl_up_sync(0xFFFFFFFFu, incl, o);
        if (lane >= o) incl += t;
    }
    if (lane == 31) warp_sums[w] = incl;
    __syncthreads();
    if (w == 0) {
        int s = warp_sums[lane];
#pragma unroll
        for (int o = 1; o < 32; o <<= 1) {
            int t = __shfl_up_sync(0xFFFFFFFFu, s, o);
            if (lane >= o) s += t;
        }
        warp_sums[lane] = s;        // inclusive over warps
    }
    __syncthreads();
    int warp_off = (w == 0) ? 0 : warp_sums[w - 1];
    if (i < N_NODES) g_rowstart[i] = warp_off + incl - v;   // block-local exclusive
    if (tid == 1023) g_blocksum[b] = warp_sums[31];
}

// ---------------- parallel CSR scan, phase B: add block prefix, write cursor ----------------
__global__ void k_scanB() {
    __shared__ int s_off;
    int b = blockIdx.x, tid = threadIdx.x;
    if (tid < 32) {
        // redundant prefix over <=49 block sums via one warp
        int acc = 0;
        for (int j = tid; j < b; j += 32) acc += g_blocksum[j];
#pragma unroll
        for (int o = 16; o > 0; o >>= 1) acc += __shfl_xor_sync(0xFFFFFFFFu, acc, o);
        if (tid == 0) s_off = acc;
    }
    __syncthreads();
    int i = b * 1024 + tid;
    if (i < N_NODES) {
        int r = g_rowstart[i] + s_off;
        g_rowstart[i] = r;
        g_cursor[i] = r;
    }
    if (b == 0 && tid == 0) g_rowstart[N_NODES] = NT;
}

__global__ void k_fill(const int* __restrict__ src, const int* __restrict__ dst) {
    int i = blockIdx.x * blockDim.x + threadIdx.x;
    if (i >= NT) return;
    int s, d;
    if (i < N_EDGES) { s = src[i]; d = dst[i]; } else { s = d = i - N_EDGES; }
    int p = atomicAdd(&g_cursor[d], 1);
    g_csrc[p] = s;
}

// ---------------- layer 1 tiled GEMM + attention logits + fused deg/wvec/pool-zero ----------------
#define G1_M 32
#define G1_SMEM (F_IN * C1 * 4 + G1_M * 43 * 4)
__global__ void __launch_bounds__(256) k_gemm1(const float* __restrict__ x,
                                               const float* __restrict__ W1,
                                               const float* __restrict__ a_s,
                                               const float* __restrict__ a_d,
                                               const int* __restrict__ dst,
                                               const float* __restrict__ W2,
                                               const float* __restrict__ as2,
                                               const float* __restrict__ ad2) {
    extern __shared__ float sm[];
    float* W1s = sm;                                  // F_IN*C1
    float (*xs)[43] = (float (*)[43])(sm + F_IN * C1);
    int tid = threadIdx.x;
    int n0 = blockIdx.x * G1_M;

    // ---- fused degree histogram (grid-stride over NT edges) ----
    for (int e = blockIdx.x * blockDim.x + tid; e < NT; e += gridDim.x * blockDim.x) {
        int d = (e < N_EDGES) ? dst[e] : e - N_EDGES;
        atomicAdd(&g_deg[d], 1);
    }
    // ---- fused wvec / pool zeroing on low blocks ----
    if (blockIdx.x < 32) {
        int k = blockIdx.x * 8 + (tid >> 5);
        int lane = tid & 31;
        float s = 0.f, d = 0.f;
#pragma unroll
        for (int j = lane; j < 256; j += 32) {
            float wv = W2[k * 256 + j];
            s += wv * as2[j];
            d += wv * ad2[j];
        }
#pragma unroll
        for (int o = 16; o > 0; o >>= 1) {
            s += __shfl_xor_sync(0xFFFFFFFFu, s, o);
            d += __shfl_xor_sync(0xFFFFFFFFu, d, o);
        }
        if (lane == 0) { g_wvs[k] = s; g_wvd[k] = d; }
    } else if (blockIdx.x < 96) {
        int idx = (blockIdx.x - 32) * 256 + tid;
        ((float4*)g_pool)[idx] = make_float4(0.f, 0.f, 0.f, 0.f);
    } else if (blockIdx.x == 96) {
        if (tid < N_GRAPHS) g_cnt[tid] = 0.f;
    }

    // ---- GEMM ----
    for (int idx = tid; idx < (F_IN * C1) / 4; idx += 256)
        ((float4*)W1s)[idx] = ((const float4*)W1)[idx];
    for (int idx = tid; idx < G1_M * F_IN; idx += 256) {
        int r = idx / F_IN, c = idx % F_IN;
        int node = n0 + r;
        xs[r][c] = (node < N_NODES) ? x[node * F_IN + c] : 0.f;
    }
    __syncthreads();

    int tr = tid >> 4, tc = tid & 15;
    int r0 = tr * 2, r1 = r0 + 1;
    float4 acc0[4], acc1[4];     // [group i] -> cols tc*4+64i .. +3
#pragma unroll
    for (int i = 0; i < 4; i++) {
        acc0[i] = make_float4(0.f, 0.f, 0.f, 0.f);
        acc1[i] = make_float4(0.f, 0.f, 0.f, 0.f);
    }

#pragma unroll 1
    for (int k = 0; k < F_IN; k++) {
        float a0 = xs[r0][k], a1 = xs[r1][k];
        const float* wrow = &W1s[k * C1 + tc * 4];
#pragma unroll
        for (int i = 0; i < 4; i++) {
            float4 b = *(const float4*)&wrow[64 * i];
            acc0[i].x += a0 * b.x; acc0[i].y += a0 * b.y;
            acc0[i].z += a0 * b.z; acc0[i].w += a0 * b.w;
            acc1[i].x += a1 * b.x; acc1[i].y += a1 * b.y;
            acc1[i].z += a1 * b.z; acc1[i].w += a1 * b.w;
        }
    }

    int node0 = n0 + r0, node1 = n0 + r1;
    float s0h0 = 0.f, s0h1 = 0.f, d0h0 = 0.f, d0h1 = 0.f;
    float s1h0 = 0.f, s1h1 = 0.f, d1h0 = 0.f, d1h1 = 0.f;
#pragma unroll
    for (int i = 0; i < 4; i++) {
        int cb = tc * 4 + 64 * i;
        float4 as = *(const float4*)&a_s[cb];
        float4 ad = *(const float4*)&a_d[cb];
        float p0s = acc0[i].x * as.x + acc0[i].y * as.y + acc0[i].z * as.z + acc0[i].w * as.w;
        float p0d = acc0[i].x * ad.x + acc0[i].y * ad.y + acc0[i].z * ad.z + acc0[i].w * ad.w;
        float p1s = acc1[i].x * as.x + acc1[i].y * as.y + acc1[i].z * as.z + acc1[i].w * as.w;
        float p1d = acc1[i].x * ad.x + acc1[i].y * ad.y + acc1[i].z * ad.z + acc1[i].w * ad.w;
        if (i < 2) { s0h0 += p0s; d0h0 += p0d; s1h0 += p1s; d1h0 += p1d; }
        else       { s0h1 += p0s; d0h1 += p0d; s1h1 += p1s; d1h1 += p1d; }
        __half2 h0a = __floats2half2_rn(acc0[i].x, acc0[i].y);
        __half2 h0b = __floats2half2_rn(acc0[i].z, acc0[i].w);
        __half2 h1a = __floats2half2_rn(acc1[i].x, acc1[i].y);
        __half2 h1b = __floats2half2_rn(acc1[i].z, acc1[i].w);
        if (node0 < N_NODES) {
            uint2 p; p.x = *(unsigned*)&h0a; p.y = *(unsigned*)&h0b;
            *(uint2*)&g_h1h[node0 * C1 + cb] = p;
        }
        if (node1 < N_NODES) {
            uint2 p; p.x = *(unsigned*)&h1a; p.y = *(unsigned*)&h1b;
            *(uint2*)&g_h1h[node1 * C1 + cb] = p;
        }
    }
#pragma unroll
    for (int o = 8; o > 0; o >>= 1) {
        s0h0 += __shfl_xor_sync(0xFFFFFFFFu, s0h0, o);
        s0h1 += __shfl_xor_sync(0xFFFFFFFFu, s0h1, o);
        d0h0 += __shfl_xor_sync(0xFFFFFFFFu, d0h0, o);
        d0h1 += __shfl_xor_sync(0xFFFFFFFFu, d0h1, o);
        s1h0 += __shfl_xor_sync(0xFFFFFFFFu, s1h0, o);
        s1h1 += __shfl_xor_sync(0xFFFFFFFFu, s1h1, o);
        d1h0 += __shfl_xor_sync(0xFFFFFFFFu, d1h0, o);
        d1h1 += __shfl_xor_sync(0xFFFFFFFFu, d1h1, o);
    }
    if (tc == 0) {
        if (node0 < N_NODES) {
            g_al_s1[node0 * 2]     = s0h0;  g_al_s1[node0 * 2 + 1] = s0h1;
            g_al_d1[node0 * 2]     = d0h0;  g_al_d1[node0 * 2 + 1] = d0h1;
        }
        if (node1 < N_NODES) {
            g_al_s1[node1 * 2]     = s1h0;  g_al_s1[node1 * 2 + 1] = s1h1;
            g_al_d1[node1 * 2]     = d1h0;  g_al_d1[node1 * 2 + 1] = d1h1;
        }
    }
}

// ---------------- layer 1 fused softmax+gather (weights hoisted) + al2 epilogue ----------------
__global__ void k_gat1(const float* __restrict__ b1) {
    int n = blockIdx.x * 8 + (threadIdx.x >> 5);
    int lane = threadIdx.x & 31;
    if (n >= N_NODES) return;
    int row = g_rowstart[n], end = g_rowstart[n + 1];
    int h = lane >> 4;
    float alD0 = g_al_d1[n * 2], alD1 = g_al_d1[n * 2 + 1];

    float den = 0.f;
    float acc[8] = {0.f, 0.f, 0.f, 0.f, 0.f, 0.f, 0.f, 0.f};
    for (int j0 = row; j0 < end; j0 += 32) {
        int idx = j0 + lane;
        bool valid = idx < end;
        int sj = valid ? __ldg(&g_csrc[idx]) : 0;
        float w0l = 0.f, w1l = 0.f;
        if (valid) {
            float2 as01 = __ldg((const float2*)&g_al_s1[sj * 2]);  // one 8B load
            w0l = __expf(lrelu(as01.x + alD0));
            w1l = __expf(lrelu(as01.y + alD1));
        }
        int cnt = min(32, end - j0);
        int k = 0;
        for (; k + 1 < cnt; k += 2) {
            int s0 = __shfl_sync(0xFFFFFFFFu, sj, k);
            int s1 = __shfl_sync(0xFFFFFFFFu, sj, k + 1);
            float w0a = __shfl_sync(0xFFFFFFFFu, w0l, k);
            float w1a = __shfl_sync(0xFFFFFFFFu, w1l, k);
            float w0b = __shfl_sync(0xFFFFFFFFu, w0l, k + 1);
            float w1b = __shfl_sync(0xFFFFFFFFu, w1l, k + 1);
            uint4 r0 = *(const uint4*)&g_h1h[s0 * C1 + lane * 8];
            uint4 r1 = *(const uint4*)&g_h1h[s1 * C1 + lane * 8];
            float wA = h ? w1a : w0a;
            float wB = h ? w1b : w0b;
            den += wA + wB;
            fma8h(acc, r0, wA);
            fma8h(acc, r1, wB);
        }
        if (k < cnt) {
            int s = __shfl_sync(0xFFFFFFFFu, sj, k);
            float w0a = __shfl_sync(0xFFFFFFFFu, w0l, k);
            float w1a = __shfl_sync(0xFFFFFFFFu, w1l, k);
            float wA = h ? w1a : w0a;
            den += wA;
            fma8h(acc, *(const uint4*)&g_h1h[s * C1 + lane * 8], wA);
        }
    }
    float inv = 1.f / (den + 1e-16f);
    int c0 = lane * 8;
    float4 o0, o1;
    o0.x = fmaxf(acc[0] * inv + b1[c0 + 0], 0.f);
    o0.y = fmaxf(acc[1] * inv + b1[c0 + 1], 0.f);
    o0.z = fmaxf(acc[2] * inv + b1[c0 + 2], 0.f);
    o0.w = fmaxf(acc[3] * inv + b1[c0 + 3], 0.f);
    o1.x = fmaxf(acc[4] * inv + b1[c0 + 4], 0.f);
    o1.y = fmaxf(acc[5] * inv + b1[c0 + 5], 0.f);
    o1.z = fmaxf(acc[6] * inv + b1[c0 + 6], 0.f);
    o1.w = fmaxf(acc[7] * inv + b1[c0 + 7], 0.f);
    *(float4*)&g_out1[n * C1 + c0] = o0;
    *(float4*)&g_out1[n * C1 + c0 + 4] = o1;

    // fused al2: al_s2[n] = relu(out1[n]) . (W2 @ as2)  (likewise d)
    float4 ws0 = *(const float4*)&g_wvs[c0], ws1 = *(const float4*)&g_wvs[c0 + 4];
    float4 wd0 = *(const float4*)&g_wvd[c0], wd1 = *(const float4*)&g_wvd[c0 + 4];
    float ps = o0.x * ws0.x + o0.y * ws0.y + o0.z * ws0.z + o0.w * ws0.w
             + o1.x * ws1.x + o1.y * ws1.y + o1.z * ws1.z + o1.w * ws1.w;
    float pd = o0.x * wd0.x + o0.y * wd0.y + o0.z * wd0.z + o0.w * wd0.w
             + o1.x * wd1.x + o1.y * wd1.y + o1.z * wd1.z + o1.w * wd1.w;
#pragma unroll
    for (int o = 16; o > 0; o >>= 1) {
        ps += __shfl_xor_sync(0xFFFFFFFFu, ps, o);
        pd += __shfl_xor_sync(0xFFFFFFFFu, pd, o);
    }
    if (lane == 0) { g_al_s2[n] = ps; g_al_d2[n] = pd; }
}

// ---------------- tf32 tensor-core GEMM, fp16 output: g_h2h = g_out1 @ W2 ----------------
#define TCM 128
#define TCN 128
#define TCK 32
__global__ void __launch_bounds__(256) k_gemm2(const float* __restrict__ A,
                                               const float* __restrict__ B,
                                               __half* __restrict__ C) {
    __shared__ __align__(16) float As[TCM][TCK + 4];   // 18.4 KB
    __shared__ __align__(16) float Bs[TCK][TCN + 4];   // 16.9 KB
    __shared__ __align__(16) float Epi[8][256];        // 8 KB: per-warp 16x16 patch
    int tid = threadIdx.x;
    int bm = blockIdx.x * TCM, bn = blockIdx.y * TCN;
    int wid = tid >> 5, lane = tid & 31;
    int warp_m = (wid >> 1) * 32, warp_n = (wid & 1) * 64;

    wmma::fragment<wmma::accumulator, 16, 16, 8, float> c_frag[2][4];
#pragma unroll
    for (int i = 0; i < 2; i++)
#pragma unroll
        for (int j = 0; j < 4; j++) wmma::fill_fragment(c_frag[i][j], 0.f);

    for (int k0 = 0; k0 < 256; k0 += TCK) {
#pragma unroll
        for (int p = 0; p < 4; p++) {
            int r = (tid >> 3) + p * 32;
            int c4 = tid & 7;
            float4 v = *(const float4*)&A[(size_t)(bm + r) * 256 + k0 + c4 * 4];
            *(float4*)&As[r][c4 * 4] = v;
        }
#pragma unroll
        for (int p = 0; p < 4; p++) {
            int r = (tid >> 5) + p * 8;
            int c4 = tid & 31;
            float4 v = *(const float4*)&B[(size_t)(k0 + r) * 256 + bn + c4 * 4];
            *(float4*)&Bs[r][c4 * 4] = v;
        }
        __syncthreads();

#pragma unroll
        for (int kk = 0; kk < TCK; kk += 8) {
            wmma::fragment<wmma::matrix_a, 16, 16, 8, wmma::precision::tf32, wmma::row_major> a_frag[2];
            wmma::fragment<wmma::matrix_b, 16, 16, 8, wmma::precision::tf32, wmma::row_major> b_frag[4];
#pragma unroll
            for (int i = 0; i < 2; i++) {
                wmma::load_matrix_sync(a_frag[i], &As[warp_m + i * 16][kk], TCK + 4);
#pragma unroll
                for (int t = 0; t < a_frag[i].num_elements; t++)
                    a_frag[i].x[t] = wmma::__float_to_tf32(a_frag[i].x[t]);
            }
#pragma unroll
            for (int j = 0; j < 4; j++) {
                wmma::load_matrix_sync(b_frag[j], &Bs[kk][warp_n + j * 16], TCN + 4);
#pragma unroll
                for (int t = 0; t < b_frag[j].num_elements; t++)
                    b_frag[j].x[t] = wmma::__float_to_tf32(b_frag[j].x[t]);
            }
#pragma unroll
            for (int i = 0; i < 2; i++)
#pragma unroll
                for (int j = 0; j < 4; j++)
                    wmma::mma_sync(c_frag[i][j], a_frag[i], b_frag[j], c_frag[i][j]);
        }
        __syncthreads();
    }

    // epilogue: stage each 16x16 fragment through smem, convert to fp16, store
    float* patch = &Epi[wid][0];
    int er = lane >> 1, ec = (lane & 1) * 8;   // each lane: 8 floats of one row
#pragma unroll
    for (int i = 0; i < 2; i++)
#pragma unroll
        for (int j = 0; j < 4; j++) {
            wmma::store_matrix_sync(patch, c_frag[i][j], 16, wmma::mem_row_major);
            __syncwarp();
            float4 a = *(float4*)&patch[er * 16 + ec];
            float4 b = *(float4*)&patch[er * 16 + ec + 4];
            __half2 hh[4];
            hh[0] = __floats2half2_rn(a.x, a.y);
            hh[1] = __floats2half2_rn(a.z, a.w);
            hh[2] = __floats2half2_rn(b.x, b.y);
            hh[3] = __floats2half2_rn(b.z, b.w);
            size_t off = (size_t)(bm + warp_m + i * 16 + er) * 256 + bn + warp_n + j * 16 + ec;
            *(uint4*)&C[off] = *(uint4*)hh;
            __syncwarp();
        }
}

// ---------------- layer 2 fused softmax+gather (weights hoisted) + bias/relu + pool ----------------
__global__ void k_gat2(const float* __restrict__ b2, const int* __restrict__ batch) {
    int n = blockIdx.x * 8 + (threadIdx.x >> 5);
    int lane = threadIdx.x & 31;
    if (n >= N_NODES) return;
    int row = g_rowstart[n], end = g_rowstart[n + 1];
    float alD = g_al_d2[n];

    float den = 0.f;
    float acc[8] = {0.f, 0.f, 0.f, 0.f, 0.f, 0.f, 0.f, 0.f};
    for (int j0 = row; j0 < end; j0 += 32) {
        int idx = j0 + lane;
        bool valid = idx < end;
        int sj = valid ? __ldg(&g_csrc[idx]) : 0;
        float wl = valid ? __expf(lrelu(__ldg(&g_al_s2[sj]) + alD)) : 0.f;
        int cnt = min(32, end - j0);
        int k = 0;
        for (; k + 1 < cnt; k += 2) {
            int s0 = __shfl_sync(0xFFFFFFFFu, sj, k);
            int s1 = __shfl_sync(0xFFFFFFFFu, sj, k + 1);
            float w0 = __shfl_sync(0xFFFFFFFFu, wl, k);
            float w1 = __shfl_sync(0xFFFFFFFFu, wl, k + 1);
            uint4 r0 = *(const uint4*)&g_h2h[s0 * C2 + lane * 8];
            uint4 r1 = *(const uint4*)&g_h2h[s1 * C2 + lane * 8];
            den += w0 + w1;
            fma8h(acc, r0, w0);
            fma8h(acc, r1, w1);
        }
        if (k < cnt) {
            int s = __shfl_sync(0xFFFFFFFFu, sj, k);
            float w = __shfl_sync(0xFFFFFFFFu, wl, k);
            den += w;
            fma8h(acc, *(const uint4*)&g_h2h[s * C2 + lane * 8], w);
        }
    }
    float inv = 1.f / (den + 1e-16f);
    int c0 = lane * 8;
    float4 o0, o1;
    o0.x = fmaxf(acc[0] * inv + b2[c0 + 0], 0.f);
    o0.y = fmaxf(acc[1] * inv + b2[c0 + 1], 0.f);
    o0.z = fmaxf(acc[2] * inv + b2[c0 + 2], 0.f);
    o0.w = fmaxf(acc[3] * inv + b2[c0 + 3], 0.f);
    o1.x = fmaxf(acc[4] * inv + b2[c0 + 4], 0.f);
    o1.y = fmaxf(acc[5] * inv + b2[c0 + 5], 0.f);
    o1.z = fmaxf(acc[6] * inv + b2[c0 + 6], 0.f);
    o1.w = fmaxf(acc[7] * inv + b2[c0 + 7], 0.f);
    int g = batch[n];
    red_add_v4(&g_pool[g * 256 + c0], o0);
    red_add_v4(&g_pool[g * 256 + c0 + 4], o1);
    if (lane == 0) atomicAdd(&g_cnt[g], 1.0f);
}

// ---------------- MLP head ----------------
__global__ void k_mlp1(const float* __restrict__ fw, const float* __restrict__ fb) {
    int g = blockIdx.x >> 2, q = blockIdx.x & 3;
    int t = threadIdx.x;
    __shared__ float grow[256];
    float inv = 1.0f / fmaxf(g_cnt[g], 1.0f);
    grow[t] = g_pool[g * 256 + t] * inv;
    __syncthreads();
    int col = q * 256 + t;
    float acc = fb[col];
#pragma unroll 8
    for (int k = 0; k < 256; k++) acc += grow[k] * fw[k * 1024 + col];
    g_fc1[g * 1024 + col] = fmaxf(acc, 0.f);
}

__global__ void k_mlp2(const float* __restrict__ fw, const float* __restrict__ fb,
                       float* __restrict__ out) {
    int g = blockIdx.x;
    int t = threadIdx.x; // 128
    __shared__ float row[1024];
    for (int k = t; k < 1024; k += 128) row[k] = g_fc1[g * 1024 + k];
    __syncthreads();
    float acc = fb[t];
#pragma unroll 8
    for (int k = 0; k < 1024; k++) acc += row[k] * fw[k * 128 + t];
    out[g * 128 + t] = acc;
}

// ---------------- host launcher ----------------
static void* sym(const void* s) {
    void* p = nullptr;
    cudaGetSymbolAddress(&p, s);
    return p;
}

extern "C" void kernel_launch(void* const* d_in, const int* in_sizes, int n_in,
                              void* d_out, int out_size) {
    const float* x      = (const float*)d_in[0];
    const int*   src    = (const int*)d_in[1];
    const int*   dst    = (const int*)d_in[2];
    const int*   batch  = (const int*)d_in[3];
    const float* W1     = (const float*)d_in[4];
    const float* a_src1 = (const float*)d_in[5];
    const float* a_dst1 = (const float*)d_in[6];
    const float* b1     = (const float*)d_in[7];
    const float* W2     = (const float*)d_in[8];
    const float* a_src2 = (const float*)d_in[9];
    const float* a_dst2 = (const float*)d_in[10];
    const float* b2     = (const float*)d_in[11];
    const float* fc1_w  = (const float*)d_in[12];
    const float* fc1_b  = (const float*)d_in[13];
    const float* fc2_w  = (const float*)d_in[14];
    const float* fc2_b  = (const float*)d_in[15];
    float* out = (float*)d_out;

    static bool attr_set = false;
    if (!attr_set) {
        cudaFuncSetAttribute(k_gemm1, cudaFuncAttributeMaxDynamicSharedMemorySize, G1_SMEM);
        attr_set = true;
    }

    cudaMemsetAsync(sym(g_deg), 0, N_NODES * sizeof(int));

    // layer-1 GEMM with fused degree histogram / wvec / pool zeroing (launch 1)
    k_gemm1<<<(N_NODES + G1_M - 1) / G1_M, 256, G1_SMEM>>>(x, W1, a_src1, a_dst1,
                                                           dst, W2, a_src2, a_dst2);
    // CSR scan (parallel, launches 2-3) + fill (launch 4)
    k_scanA<<<SCAN_BLOCKS, 1024>>>();
    k_scanB<<<SCAN_BLOCKS, 1024>>>();
    k_fill<<<(NT + 255) / 256, 256>>>(src, dst);

    // layer-1 gather
    k_gat1<<<(N_NODES + 7) / 8, 256>>>(b1);

    // layer 2 (tf32 tensor cores, fp16 output, padded rows)
    float* d_o1 = (float*)sym(g_out1);
    __half* d_h2h = (__half*)sym(g_h2h);
    dim3 g2(N_PAD / TCM, 256 / TCN);
    k_gemm2<<<g2, 256>>>(d_o1, W2, d_h2h);
    k_gat2<<<(N_NODES + 7) / 8, 256>>>(b2, batch);

    // MLP
    k_mlp1<<<N_GRAPHS * 4, 256>>>(fc1_w, fc1_b);
    k_mlp2<<<N_GRAPHS, 128>>>(fc2_w, fc2_b, out);
}